// round 1
// baseline (speedup 1.0000x reference)
#include <cuda_runtime.h>

// RBF kernel: out[i,c] = sum_j exp(-g * max(||x_i||^2 + ||y_j||^2 - 2 x_i.y_j, 0)) * b[j,c]
// N = M = 16384, D = 32, Dv = 16.  fp32 throughout, packed f32x2 FMAs (Blackwell FFMA2).

#define N_PTS   16384
#define M_PTS   16384
#define D_DIM   32
#define DV      16
#define BI      64      // i-rows per CTA
#define BJ      128     // j-rows per smem tile
#define THREADS 256     // 64 i-lanes x 4 j-slices
#define PSTRIDE 68      // floats per j-pair row in sy (64 data + 4 pad, keeps 16B align, spreads banks)

__device__ float g_yn[M_PTS];   // precomputed ||y_j||^2 scratch (static device global, no alloc)

// ---- f32x2 helpers (PTX-only on Blackwell; ptxas never auto-fuses) ----
__device__ __forceinline__ unsigned long long pack2(float lo, float hi) {
    unsigned long long r;
    asm("mov.b64 %0, {%1, %2};" : "=l"(r) : "f"(lo), "f"(hi));
    return r;
}
__device__ __forceinline__ void unpack2(unsigned long long v, float& lo, float& hi) {
    asm("mov.b64 {%0, %1}, %2;" : "=f"(lo), "=f"(hi) : "l"(v));
}
__device__ __forceinline__ unsigned long long ffma2(unsigned long long a, unsigned long long b,
                                                    unsigned long long c) {
    unsigned long long d;
    asm("fma.rn.f32x2 %0, %1, %2, %3;" : "=l"(d) : "l"(a), "l"(b), "l"(c));
    return d;
}
__device__ __forceinline__ unsigned long long fadd2(unsigned long long a, unsigned long long b) {
    unsigned long long d;
    asm("add.rn.f32x2 %0, %1, %2;" : "=l"(d) : "l"(a), "l"(b));
    return d;
}
__device__ __forceinline__ unsigned long long fmul2(unsigned long long a, unsigned long long b) {
    unsigned long long d;
    asm("mul.rn.f32x2 %0, %1, %2;" : "=l"(d) : "l"(a), "l"(b));
    return d;
}
__device__ __forceinline__ float ex2_approx(float a) {
    float r;
    asm("ex2.approx.ftz.f32 %0, %1;" : "=f"(r) : "f"(a));
    return r;
}

// ---- kernel 1: yn[j] = ||y_j||^2 ----
__global__ void yn_kernel(const float* __restrict__ y) {
    int j = blockIdx.x * blockDim.x + threadIdx.x;
    const float4* r = (const float4*)(y + (long)j * D_DIM);
    float s = 0.f;
#pragma unroll
    for (int q = 0; q < D_DIM / 4; q++) {
        float4 v = r[q];
        s += v.x * v.x + v.y * v.y + v.z * v.z + v.w * v.w;
    }
    g_yn[j] = s;
}

// ---- kernel 2: main RBF matvec ----
__global__ void __launch_bounds__(THREADS, 2)
rbf_kernel(const float* __restrict__ ls, const float* __restrict__ x,
           const float* __restrict__ y, const float* __restrict__ b,
           float* __restrict__ out) {
    __shared__ __align__(16) float sy[(BJ / 2) * PSTRIDE];  // y tile, j-pair interleaved: 4352 f
    __shared__ __align__(16) float sb[BJ * DV];             // b tile: 2048 f
    __shared__ __align__(16) float syn[BJ];                 // yn tile as 64 float2

    const int tid = threadIdx.x;
    const int il  = tid & (BI - 1);   // i-lane within CTA
    const int s   = tid >> 6;         // j-slice 0..3
    const int i   = blockIdx.x * BI + il;

    // Load x_i, build duplicated-packed xd[k] = (x_k, x_k), and xn = ||x_i||^2
    unsigned long long xd[D_DIM];
    float xn = 0.f;
    {
        const float4* xr = (const float4*)(x + (long)i * D_DIM);
#pragma unroll
        for (int q = 0; q < D_DIM / 4; q++) {
            float4 v = xr[q];
            xn += v.x * v.x + v.y * v.y + v.z * v.z + v.w * v.w;
            xd[q * 4 + 0] = pack2(v.x, v.x);
            xd[q * 4 + 1] = pack2(v.y, v.y);
            xd[q * 4 + 2] = pack2(v.z, v.z);
            xd[q * 4 + 3] = pack2(v.w, v.w);
        }
    }
    const float g    = __ldg(ls);
    const float cneg = -g * 1.4426950408889634f;  // -g * log2(e)
    const unsigned long long cneg2 = pack2(cneg, cneg);
    const unsigned long long xn2   = pack2(xn, xn);
    const unsigned long long m2    = pack2(-2.f, -2.f);

    unsigned long long acc[DV / 2];
#pragma unroll
    for (int c = 0; c < DV / 2; c++) acc[c] = 0ull;

    const int pbase = s * 16;  // 16 j-pairs per slice per tile

    for (int t = 0; t < M_PTS / BJ; t++) {
        const int jbase = t * BJ;
        __syncthreads();  // previous tile fully consumed

        // --- stage y tile, j-pair interleaved: sy[p*PSTRIDE + 2k + parity] ---
        {
            int p = tid >> 2, kq = tid & 3;  // p: j-pair 0..63, kq: k-quarter 0..3
            const float4* r0 = (const float4*)(y + (long)(jbase + 2 * p) * D_DIM + kq * 8);
            const float4* r1 = (const float4*)(y + (long)(jbase + 2 * p + 1) * D_DIM + kq * 8);
            float4 a0 = r0[0], a1 = r0[1];
            float4 c0 = r1[0], c1 = r1[1];
            float2* dst = (float2*)(sy + p * PSTRIDE + kq * 16);
            dst[0] = make_float2(a0.x, c0.x);
            dst[1] = make_float2(a0.y, c0.y);
            dst[2] = make_float2(a0.z, c0.z);
            dst[3] = make_float2(a0.w, c0.w);
            dst[4] = make_float2(a1.x, c1.x);
            dst[5] = make_float2(a1.y, c1.y);
            dst[6] = make_float2(a1.z, c1.z);
            dst[7] = make_float2(a1.w, c1.w);
        }
        // --- stage b tile (natural layout) ---
        {
            int row = tid >> 1, half = tid & 1;
            const float4* rb = (const float4*)(b + (long)(jbase + row) * DV + half * 8);
            float4 v0 = rb[0], v1 = rb[1];
            float4* dst = (float4*)(sb + row * DV + half * 8);
            dst[0] = v0;
            dst[1] = v1;
        }
        // --- stage yn pairs ---
        if (tid < BJ / 2) {
            ((float2*)syn)[tid] = make_float2(g_yn[jbase + 2 * tid], g_yn[jbase + 2 * tid + 1]);
        }
        __syncthreads();

#pragma unroll 1
        for (int p16 = 0; p16 < 16; p16++) {
            const int p = pbase + p16;
            const float* yrow = sy + p * PSTRIDE;

            // dot products for (j0, j1) in one packed lane; 4 independent chains
            unsigned long long d0 = 0ull, d1 = 0ull, d2 = 0ull, d3 = 0ull;
#pragma unroll
            for (int k4 = 0; k4 < 16; k4 += 4) {
                ulonglong2 ua = ((const ulonglong2*)yrow)[k4 + 0];  // k = 2k4, 2k4+1
                ulonglong2 ub = ((const ulonglong2*)yrow)[k4 + 1];
                ulonglong2 uc = ((const ulonglong2*)yrow)[k4 + 2];
                ulonglong2 ud = ((const ulonglong2*)yrow)[k4 + 3];
                d0 = ffma2(xd[2 * k4 + 0], ua.x, d0);
                d0 = ffma2(xd[2 * k4 + 1], ua.y, d0);
                d1 = ffma2(xd[2 * k4 + 2], ub.x, d1);
                d1 = ffma2(xd[2 * k4 + 3], ub.y, d1);
                d2 = ffma2(xd[2 * k4 + 4], uc.x, d2);
                d2 = ffma2(xd[2 * k4 + 5], uc.y, d2);
                d3 = ffma2(xd[2 * k4 + 6], ud.x, d3);
                d3 = ffma2(xd[2 * k4 + 7], ud.y, d3);
            }
            unsigned long long dd  = fadd2(fadd2(d0, d1), fadd2(d2, d3));
            unsigned long long tyn = fadd2(xn2, ((const unsigned long long*)syn)[p]);
            unsigned long long sq  = ffma2(m2, dd, tyn);          // xn + yn - 2*dot
            unsigned long long a2  = fmul2(cneg2, sq);            // cneg * sq
            float a0, a1;
            unpack2(a2, a0, a1);
            // max(sq,0)*cneg == min(sq*cneg, 0) since cneg <= 0
            float w0 = ex2_approx(fminf(a0, 0.f));
            float w1 = ex2_approx(fminf(a1, 0.f));
            unsigned long long w0d = pack2(w0, w0);
            unsigned long long w1d = pack2(w1, w1);

            const ulonglong2* b0p = (const ulonglong2*)(sb + (2 * p) * DV);
            const ulonglong2* b1p = (const ulonglong2*)(sb + (2 * p + 1) * DV);
#pragma unroll
            for (int c4 = 0; c4 < 4; c4++) {
                ulonglong2 bb = b0p[c4];
                acc[c4 * 2 + 0] = ffma2(w0d, bb.x, acc[c4 * 2 + 0]);
                acc[c4 * 2 + 1] = ffma2(w0d, bb.y, acc[c4 * 2 + 1]);
            }
#pragma unroll
            for (int c4 = 0; c4 < 4; c4++) {
                ulonglong2 bb = b1p[c4];
                acc[c4 * 2 + 0] = ffma2(w1d, bb.x, acc[c4 * 2 + 0]);
                acc[c4 * 2 + 1] = ffma2(w1d, bb.y, acc[c4 * 2 + 1]);
            }
        }
    }

    // ---- deterministic cross-slice reduction through smem (reuse sy: 4096 floats needed) ----
    __syncthreads();
    float* red = sy;
#pragma unroll
    for (int cp = 0; cp < DV / 2; cp++) {
        float lo, hi;
        unpack2(acc[cp], lo, hi);
        red[(s * BI + il) * DV + 2 * cp + 0] = lo;
        red[(s * BI + il) * DV + 2 * cp + 1] = hi;
    }
    __syncthreads();
    {
        float4 r0 = ((const float4*)red)[tid + 0];
        float4 r1 = ((const float4*)red)[tid + 256];
        float4 r2 = ((const float4*)red)[tid + 512];
        float4 r3 = ((const float4*)red)[tid + 768];
        float4 o;
        o.x = r0.x + r1.x + r2.x + r3.x;   // fixed order: slice 0,1,2,3 -> deterministic
        o.y = r0.y + r1.y + r2.y + r3.y;
        o.z = r0.z + r1.z + r2.z + r3.z;
        o.w = r0.w + r1.w + r2.w + r3.w;
        ((float4*)out)[(long)blockIdx.x * 256 + tid] = o;
    }
}

extern "C" void kernel_launch(void* const* d_in, const int* in_sizes, int n_in,
                              void* d_out, int out_size) {
    const float* ls = (const float*)d_in[0];
    const float* x  = (const float*)d_in[1];
    const float* y  = (const float*)d_in[2];
    const float* b  = (const float*)d_in[3];
    float* out = (float*)d_out;

    yn_kernel<<<M_PTS / 256, 256>>>(y);
    rbf_kernel<<<N_PTS / BI, THREADS>>>(ls, x, y, b, out);
}

// round 2
// speedup vs baseline: 1.0005x; 1.0005x over previous
#include <cuda_runtime.h>

// RBF kernel: out[i,c] = sum_j exp(-g * max(||x_i||^2 + ||y_j||^2 - 2 x_i.y_j, 0)) * b[j,c]
// N = M = 16384, D = 32, Dv = 16.  fp32 throughout, packed f32x2 FMAs (Blackwell FFMA2).

#define N_PTS   16384
#define M_PTS   16384
#define D_DIM   32
#define DV      16
#define BI      64      // i-rows per CTA
#define BJ      128     // j-rows per smem tile
#define THREADS 256     // 64 i-lanes x 4 j-slices
#define PSTRIDE 68      // floats per j-pair row in sy (64 data + 4 pad, keeps 16B align, spreads banks)

__device__ float g_yn[M_PTS];   // precomputed ||y_j||^2 scratch (static device global, no alloc)

// ---- f32x2 helpers (PTX-only on Blackwell; ptxas never auto-fuses) ----
__device__ __forceinline__ unsigned long long pack2(float lo, float hi) {
    unsigned long long r;
    asm("mov.b64 %0, {%1, %2};" : "=l"(r) : "f"(lo), "f"(hi));
    return r;
}
__device__ __forceinline__ void unpack2(unsigned long long v, float& lo, float& hi) {
    asm("mov.b64 {%0, %1}, %2;" : "=f"(lo), "=f"(hi) : "l"(v));
}
__device__ __forceinline__ unsigned long long ffma2(unsigned long long a, unsigned long long b,
                                                    unsigned long long c) {
    unsigned long long d;
    asm("fma.rn.f32x2 %0, %1, %2, %3;" : "=l"(d) : "l"(a), "l"(b), "l"(c));
    return d;
}
__device__ __forceinline__ unsigned long long fadd2(unsigned long long a, unsigned long long b) {
    unsigned long long d;
    asm("add.rn.f32x2 %0, %1, %2;" : "=l"(d) : "l"(a), "l"(b));
    return d;
}
__device__ __forceinline__ unsigned long long fmul2(unsigned long long a, unsigned long long b) {
    unsigned long long d;
    asm("mul.rn.f32x2 %0, %1, %2;" : "=l"(d) : "l"(a), "l"(b));
    return d;
}
__device__ __forceinline__ float ex2_approx(float a) {
    float r;
    asm("ex2.approx.ftz.f32 %0, %1;" : "=f"(r) : "f"(a));
    return r;
}

// ---- kernel 1: yn[j] = ||y_j||^2 ----
__global__ void yn_kernel(const float* __restrict__ y) {
    int j = blockIdx.x * blockDim.x + threadIdx.x;
    const float4* r = (const float4*)(y + (long)j * D_DIM);
    float s = 0.f;
#pragma unroll
    for (int q = 0; q < D_DIM / 4; q++) {
        float4 v = r[q];
        s += v.x * v.x + v.y * v.y + v.z * v.z + v.w * v.w;
    }
    g_yn[j] = s;
}

// ---- kernel 2: main RBF matvec ----
__global__ void __launch_bounds__(THREADS, 2)
rbf_kernel(const float* __restrict__ ls, const float* __restrict__ x,
           const float* __restrict__ y, const float* __restrict__ b,
           float* __restrict__ out) {
    __shared__ __align__(16) float sy[(BJ / 2) * PSTRIDE];  // y tile, j-pair interleaved: 4352 f
    __shared__ __align__(16) float sb[BJ * DV];             // b tile: 2048 f
    __shared__ __align__(16) float syn[BJ];                 // yn tile as 64 float2

    const int tid = threadIdx.x;
    const int il  = tid & (BI - 1);   // i-lane within CTA
    const int s   = tid >> 6;         // j-slice 0..3
    const int i   = blockIdx.x * BI + il;

    // Load x_i, build duplicated-packed xd[k] = (x_k, x_k), and xn = ||x_i||^2
    unsigned long long xd[D_DIM];
    float xn = 0.f;
    {
        const float4* xr = (const float4*)(x + (long)i * D_DIM);
#pragma unroll
        for (int q = 0; q < D_DIM / 4; q++) {
            float4 v = xr[q];
            xn += v.x * v.x + v.y * v.y + v.z * v.z + v.w * v.w;
            xd[q * 4 + 0] = pack2(v.x, v.x);
            xd[q * 4 + 1] = pack2(v.y, v.y);
            xd[q * 4 + 2] = pack2(v.z, v.z);
            xd[q * 4 + 3] = pack2(v.w, v.w);
        }
    }
    const float g    = __ldg(ls);
    const float cneg = -g * 1.4426950408889634f;  // -g * log2(e)
    const unsigned long long cneg2 = pack2(cneg, cneg);
    const unsigned long long xn2   = pack2(xn, xn);
    const unsigned long long m2    = pack2(-2.f, -2.f);

    unsigned long long acc[DV / 2];
#pragma unroll
    for (int c = 0; c < DV / 2; c++) acc[c] = 0ull;

    const int pbase = s * 16;  // 16 j-pairs per slice per tile

    for (int t = 0; t < M_PTS / BJ; t++) {
        const int jbase = t * BJ;
        __syncthreads();  // previous tile fully consumed

        // --- stage y tile, j-pair interleaved: sy[p*PSTRIDE + 2k + parity] ---
        {
            int p = tid >> 2, kq = tid & 3;  // p: j-pair 0..63, kq: k-quarter 0..3
            const float4* r0 = (const float4*)(y + (long)(jbase + 2 * p) * D_DIM + kq * 8);
            const float4* r1 = (const float4*)(y + (long)(jbase + 2 * p + 1) * D_DIM + kq * 8);
            float4 a0 = r0[0], a1 = r0[1];
            float4 c0 = r1[0], c1 = r1[1];
            float2* dst = (float2*)(sy + p * PSTRIDE + kq * 16);
            dst[0] = make_float2(a0.x, c0.x);
            dst[1] = make_float2(a0.y, c0.y);
            dst[2] = make_float2(a0.z, c0.z);
            dst[3] = make_float2(a0.w, c0.w);
            dst[4] = make_float2(a1.x, c1.x);
            dst[5] = make_float2(a1.y, c1.y);
            dst[6] = make_float2(a1.z, c1.z);
            dst[7] = make_float2(a1.w, c1.w);
        }
        // --- stage b tile (natural layout) ---
        {
            int row = tid >> 1, half = tid & 1;
            const float4* rb = (const float4*)(b + (long)(jbase + row) * DV + half * 8);
            float4 v0 = rb[0], v1 = rb[1];
            float4* dst = (float4*)(sb + row * DV + half * 8);
            dst[0] = v0;
            dst[1] = v1;
        }
        // --- stage yn pairs ---
        if (tid < BJ / 2) {
            ((float2*)syn)[tid] = make_float2(g_yn[jbase + 2 * tid], g_yn[jbase + 2 * tid + 1]);
        }
        __syncthreads();

#pragma unroll 1
        for (int p16 = 0; p16 < 16; p16++) {
            const int p = pbase + p16;
            const float* yrow = sy + p * PSTRIDE;

            // dot products for (j0, j1) in one packed lane; 4 independent chains
            unsigned long long d0 = 0ull, d1 = 0ull, d2 = 0ull, d3 = 0ull;
#pragma unroll
            for (int k4 = 0; k4 < 16; k4 += 4) {
                ulonglong2 ua = ((const ulonglong2*)yrow)[k4 + 0];  // k = 2k4, 2k4+1
                ulonglong2 ub = ((const ulonglong2*)yrow)[k4 + 1];
                ulonglong2 uc = ((const ulonglong2*)yrow)[k4 + 2];
                ulonglong2 ud = ((const ulonglong2*)yrow)[k4 + 3];
                d0 = ffma2(xd[2 * k4 + 0], ua.x, d0);
                d0 = ffma2(xd[2 * k4 + 1], ua.y, d0);
                d1 = ffma2(xd[2 * k4 + 2], ub.x, d1);
                d1 = ffma2(xd[2 * k4 + 3], ub.y, d1);
                d2 = ffma2(xd[2 * k4 + 4], uc.x, d2);
                d2 = ffma2(xd[2 * k4 + 5], uc.y, d2);
                d3 = ffma2(xd[2 * k4 + 6], ud.x, d3);
                d3 = ffma2(xd[2 * k4 + 7], ud.y, d3);
            }
            unsigned long long dd  = fadd2(fadd2(d0, d1), fadd2(d2, d3));
            unsigned long long tyn = fadd2(xn2, ((const unsigned long long*)syn)[p]);
            unsigned long long sq  = ffma2(m2, dd, tyn);          // xn + yn - 2*dot
            unsigned long long a2  = fmul2(cneg2, sq);            // cneg * sq
            float a0, a1;
            unpack2(a2, a0, a1);
            // max(sq,0)*cneg == min(sq*cneg, 0) since cneg <= 0
            float w0 = ex2_approx(fminf(a0, 0.f));
            float w1 = ex2_approx(fminf(a1, 0.f));
            unsigned long long w0d = pack2(w0, w0);
            unsigned long long w1d = pack2(w1, w1);

            const ulonglong2* b0p = (const ulonglong2*)(sb + (2 * p) * DV);
            const ulonglong2* b1p = (const ulonglong2*)(sb + (2 * p + 1) * DV);
#pragma unroll
            for (int c4 = 0; c4 < 4; c4++) {
                ulonglong2 bb = b0p[c4];
                acc[c4 * 2 + 0] = ffma2(w0d, bb.x, acc[c4 * 2 + 0]);
                acc[c4 * 2 + 1] = ffma2(w0d, bb.y, acc[c4 * 2 + 1]);
            }
#pragma unroll
            for (int c4 = 0; c4 < 4; c4++) {
                ulonglong2 bb = b1p[c4];
                acc[c4 * 2 + 0] = ffma2(w1d, bb.x, acc[c4 * 2 + 0]);
                acc[c4 * 2 + 1] = ffma2(w1d, bb.y, acc[c4 * 2 + 1]);
            }
        }
    }

    // ---- deterministic cross-slice reduction through smem (reuse sy: 4096 floats needed) ----
    __syncthreads();
    float* red = sy;
#pragma unroll
    for (int cp = 0; cp < DV / 2; cp++) {
        float lo, hi;
        unpack2(acc[cp], lo, hi);
        red[(s * BI + il) * DV + 2 * cp + 0] = lo;
        red[(s * BI + il) * DV + 2 * cp + 1] = hi;
    }
    __syncthreads();
    {
        float4 r0 = ((const float4*)red)[tid + 0];
        float4 r1 = ((const float4*)red)[tid + 256];
        float4 r2 = ((const float4*)red)[tid + 512];
        float4 r3 = ((const float4*)red)[tid + 768];
        float4 o;
        o.x = r0.x + r1.x + r2.x + r3.x;   // fixed order: slice 0,1,2,3 -> deterministic
        o.y = r0.y + r1.y + r2.y + r3.y;
        o.z = r0.z + r1.z + r2.z + r3.z;
        o.w = r0.w + r1.w + r2.w + r3.w;
        ((float4*)out)[(long)blockIdx.x * 256 + tid] = o;
    }
}

extern "C" void kernel_launch(void* const* d_in, const int* in_sizes, int n_in,
                              void* d_out, int out_size) {
    const float* ls = (const float*)d_in[0];
    const float* x  = (const float*)d_in[1];
    const float* y  = (const float*)d_in[2];
    const float* b  = (const float*)d_in[3];
    float* out = (float*)d_out;

    yn_kernel<<<M_PTS / 256, 256>>>(y);
    rbf_kernel<<<N_PTS / BI, THREADS>>>(ls, x, y, b, out);
}

// round 4
// speedup vs baseline: 3.0105x; 3.0092x over previous
#include <cuda_runtime.h>
#include <cuda_bf16.h>
#include <cstdint>

#define LOG2E 1.4426950408889634f
#define NP  16384
#define NT  256      // j-tiles of 64
#define NWG 1024     // i row-groups of 16

// ---- static device scratch: fragment-major operand images (no allocation) ----
__device__ uint32_t g_Xf[NWG * 32 * 16];  // per rowgroup: [lane][16 regs] = 2MB
__device__ uint32_t g_Yf[NT * 2048];      // per tile: [nb(8)][lane][8 regs] = 2MB
__device__ uint32_t g_Bf[NT * 1024];      // per tile: [fp(8)][lane][4 regs] = 1MB
__device__ float g_cxn[NP];
__device__ float g_cyn[NP];

// ---- helpers ----
__device__ __forceinline__ uint32_t smem_u32(const void* p) {
    uint32_t a;
    asm("{ .reg .u64 t; cvta.to.shared.u64 t, %1; cvt.u32.u64 %0, t; }" : "=r"(a) : "l"(p));
    return a;
}
__device__ __forceinline__ void cp16(uint32_t d, const void* s) {
    asm volatile("cp.async.cg.shared.global [%0], [%1], 16;" :: "r"(d), "l"(s));
}
#define CP_COMMIT() asm volatile("cp.async.commit_group;" ::: "memory")
#define CP_WAIT0()  asm volatile("cp.async.wait_group 0;" ::: "memory")

__device__ __forceinline__ void mma_bf16(float* d, const uint32_t* a, uint32_t b0, uint32_t b1) {
    asm volatile("mma.sync.aligned.m16n8k16.row.col.f32.bf16.bf16.f32 "
                 "{%0,%1,%2,%3},{%4,%5,%6,%7},{%8,%9},{%0,%1,%2,%3};"
                 : "+f"(d[0]), "+f"(d[1]), "+f"(d[2]), "+f"(d[3])
                 : "r"(a[0]), "r"(a[1]), "r"(a[2]), "r"(a[3]), "r"(b0), "r"(b1));
}
__device__ __forceinline__ float ex2f(float a) {
    float r; asm("ex2.approx.ftz.f32 %0, %1;" : "=f"(r) : "f"(a)); return r;
}
__device__ __forceinline__ uint32_t pk2(float lo, float hi) {  // bf16x2, lo in low half
    __nv_bfloat162 h = __float22bfloat162_rn(make_float2(lo, hi));
    return *(uint32_t*)&h;
}
__device__ __forceinline__ float bflo(uint32_t u) { return __uint_as_float(u << 16); }
__device__ __forceinline__ float bfhi(uint32_t u) { return __uint_as_float(u & 0xffff0000u); }
__device__ __forceinline__ uint32_t pk_split(float a, float b, int low) {
    float ah = __bfloat162float(__float2bfloat16(a));
    float bh = __bfloat162float(__float2bfloat16(b));
    return low ? pk2(a - ah, b - bh) : pk2(ah, bh);
}

// ================= prep kernels: build fragment-major images =================

// X a-frags: thread = (rowgroup wg, lane l). Also computes cxn for its 2 rows.
__global__ void prep_x(const float* __restrict__ ls, const float* __restrict__ x) {
    int t = blockIdx.x * 128 + threadIdx.x;       // 0..32767
    int wg = t >> 5, l = t & 31;
    int r0 = wg * 16 + (l >> 2), r1 = r0 + 8;
    int c = 2 * (l & 3);
    const float* x0 = x + (size_t)r0 * 32;
    const float* x1 = x + (size_t)r1 * 32;
    float v0[8], v1[8], n0 = 0.f, n1 = 0.f;
#pragma unroll
    for (int kf = 0; kf < 2; kf++)
#pragma unroll
        for (int h = 0; h < 2; h++)
#pragma unroll
            for (int e = 0; e < 2; e++) {
                int idx = kf * 4 + h * 2 + e;
                int col = kf * 16 + h * 8 + c + e;
                v0[idx] = x0[col]; v1[idx] = x1[col];
                n0 += v0[idx] * v0[idx];
                n1 += v1[idx] * v1[idx];
            }
    n0 += __shfl_xor_sync(0xffffffffu, n0, 1); n0 += __shfl_xor_sync(0xffffffffu, n0, 2);
    n1 += __shfl_xor_sync(0xffffffffu, n1, 1); n1 += __shfl_xor_sync(0xffffffffu, n1, 2);
    const float cneg = -ls[0] * LOG2E;
    if ((l & 3) == 0) { g_cxn[r0] = cneg * n0; g_cxn[r1] = cneg * n1; }

    uint32_t o[16];
#pragma unroll
    for (int s = 0; s < 2; s++)
#pragma unroll
        for (int kf = 0; kf < 2; kf++)
#pragma unroll
            for (int h = 0; h < 2; h++) {
                // frag (s,kf) quads: [h*2+0]=(r0, k half h), [h*2+1]=(r1, k half h)
                o[s * 8 + kf * 4 + h * 2 + 0] = pk_split(v0[kf * 4 + h * 2], v0[kf * 4 + h * 2 + 1], s);
                o[s * 8 + kf * 4 + h * 2 + 1] = pk_split(v1[kf * 4 + h * 2], v1[kf * 4 + h * 2 + 1], s);
            }
    uint4* dst = (uint4*)(g_Xf + (size_t)t * 16);
#pragma unroll
    for (int q = 0; q < 4; q++) dst[q] = make_uint4(o[4 * q], o[4 * q + 1], o[4 * q + 2], o[4 * q + 3]);
}

// Y b-frags: thread = (tile*8+nb, lane). Also computes cyn.
__global__ void prep_y(const float* __restrict__ ls, const float* __restrict__ y) {
    int t = blockIdx.x * 128 + threadIdx.x;       // 0..65535
    int tn = t >> 5, l = t & 31;
    int j = tn * 8 + (l >> 2);
    int c = 2 * (l & 3);
    const float* yr = y + (size_t)j * 32;
    float v[8], n = 0.f;
#pragma unroll
    for (int kf = 0; kf < 2; kf++)
#pragma unroll
        for (int h = 0; h < 2; h++)
#pragma unroll
            for (int e = 0; e < 2; e++) {
                int idx = kf * 4 + h * 2 + e;
                v[idx] = yr[kf * 16 + h * 8 + c + e];
                n += v[idx] * v[idx];
            }
    n += __shfl_xor_sync(0xffffffffu, n, 1); n += __shfl_xor_sync(0xffffffffu, n, 2);
    if ((l & 3) == 0) g_cyn[j] = -ls[0] * LOG2E * n;

    uint32_t o[8];
#pragma unroll
    for (int s = 0; s < 2; s++)
#pragma unroll
        for (int kf = 0; kf < 2; kf++)
#pragma unroll
            for (int h = 0; h < 2; h++)
                o[s * 4 + kf * 2 + h] = pk_split(v[kf * 4 + h * 2], v[kf * 4 + h * 2 + 1], s);
    uint4* dst = (uint4*)(g_Yf + (size_t)tn * 256 + l * 8);
    dst[0] = make_uint4(o[0], o[1], o[2], o[3]);
    dst[1] = make_uint4(o[4], o[5], o[6], o[7]);
}

// B b-frags (GEMM2): thread = (tile*8+fp, lane); fp = kf*2 + nb2.
__global__ void prep_b(const float* __restrict__ b) {
    int t = blockIdx.x * 128 + threadIdx.x;       // 0..65535
    int u = t >> 5, l = t & 31;
    int tile = u >> 3, fp = u & 7, kf = fp >> 1, nb2 = fp & 1;
    int c = nb2 * 8 + (l >> 2);
    int jb = tile * 64 + kf * 16 + 2 * (l & 3);
    float p0 = b[(size_t)jb * 16 + c];
    float p1 = b[(size_t)(jb + 1) * 16 + c];
    float p2 = b[(size_t)(jb + 8) * 16 + c];
    float p3 = b[(size_t)(jb + 9) * 16 + c];
    uint32_t h0 = pk_split(p0, p1, 0), h1 = pk_split(p2, p3, 0);
    uint32_t l0 = pk_split(p0, p1, 1), l1 = pk_split(p2, p3, 1);
    *(uint4*)(g_Bf + (size_t)tile * 1024 + fp * 128 + l * 4) = make_uint4(h0, h1, l0, l1);
}

// ================= main kernel =================
// smem: SY 2x8192 @0, SB 2x4096 @16384, SCY 2x256 @24576
#define SMEM_BYTES 25088

__device__ __forceinline__ void issue_loads(uint32_t smb, int tile, int buf, int tid) {
    const char* gy = (const char*)g_Yf + (size_t)tile * 8192;
    uint32_t dy = smb + buf * 8192;
#pragma unroll
    for (int k = 0; k < 4; k++) cp16(dy + (tid + k * 128) * 16, gy + (size_t)(tid + k * 128) * 16);
    const char* gb = (const char*)g_Bf + (size_t)tile * 4096;
    uint32_t db = smb + 16384 + buf * 4096;
#pragma unroll
    for (int k = 0; k < 2; k++) cp16(db + (tid + k * 128) * 16, gb + (size_t)(tid + k * 128) * 16);
    if (tid < 16) cp16(smb + 24576 + buf * 256 + tid * 16, (const char*)(g_cyn + tile * 64) + tid * 16);
}

__global__ void __launch_bounds__(128)
rbf_main(const float* __restrict__ ls, float* __restrict__ out) {
    __shared__ __align__(16) char sm[SMEM_BYTES];
    const uint32_t smb = smem_u32(sm);
    const int tid = threadIdx.x, w = tid >> 5, l = tid & 31;
    const int bidx = blockIdx.x;
    const int ig = bidx * 64 + w * 16;

    // persistent X a-frags: [Xh kf0 | Xh kf1 | Xl kf0 | Xl kf1], 4 regs each
    uint32_t xf[16];
    {
        const uint4* p = (const uint4*)(g_Xf + ((size_t)(bidx * 4 + w) * 32 + l) * 16);
#pragma unroll
        for (int q = 0; q < 4; q++) *(uint4*)(xf + 4 * q) = p[q];
    }
    const float cxnA = g_cxn[ig + (l >> 2)];
    const float cxnB = g_cxn[ig + (l >> 2) + 8];
    const float C2 = 2.f * __ldg(ls) * LOG2E;

    float o0[4] = {0.f, 0.f, 0.f, 0.f}, o1[4] = {0.f, 0.f, 0.f, 0.f};

    issue_loads(smb, 0, 0, tid);
    CP_COMMIT();

    for (int t = 0; t < NT; t++) {
        CP_WAIT0();
        __syncthreads();
        if (t + 1 < NT) { issue_loads(smb, t + 1, (t + 1) & 1, tid); CP_COMMIT(); }
        const int buf = t & 1;
        const char* syb = sm + buf * 8192;
        const char* sbb = sm + 16384 + buf * 4096;
        const char* scy = sm + 24576 + buf * 256;

        uint32_t wah[4][4], wal[4][4];
#pragma unroll
        for (int nb = 0; nb < 8; nb++) {
            uint4 y0 = *(const uint4*)(syb + nb * 1024 + l * 32);
            uint4 y1 = *(const uint4*)(syb + nb * 1024 + l * 32 + 16);
            float s[4] = {0.f, 0.f, 0.f, 0.f};
            mma_bf16(s, xf + 0,  y0.x, y0.y);   // Xh kf0 · Yh kf0
            mma_bf16(s, xf + 4,  y0.z, y0.w);   // Xh kf1 · Yh kf1
            mma_bf16(s, xf + 0,  y1.x, y1.y);   // Xh kf0 · Yl kf0
            mma_bf16(s, xf + 4,  y1.z, y1.w);   // Xh kf1 · Yl kf1
            mma_bf16(s, xf + 8,  y0.x, y0.y);   // Xl kf0 · Yh kf0
            mma_bf16(s, xf + 12, y0.z, y0.w);   // Xl kf1 · Yh kf1

            float2 cy = *(const float2*)(scy + nb * 32 + (l & 3) * 8);
            float w0 = ex2f(fminf(fmaf(C2, s[0], cxnA + cy.x), 0.f));
            float w1 = ex2f(fminf(fmaf(C2, s[1], cxnA + cy.y), 0.f));
            float w2 = ex2f(fminf(fmaf(C2, s[2], cxnB + cy.x), 0.f));
            float w3 = ex2f(fminf(fmaf(C2, s[3], cxnB + cy.y), 0.f));
            uint32_t h01 = pk2(w0, w1), h23 = pk2(w2, w3);
            uint32_t l01 = pk2(w0 - bflo(h01), w1 - bfhi(h01));
            uint32_t l23 = pk2(w2 - bflo(h23), w3 - bfhi(h23));
            const int g = nb >> 1, q = (nb & 1) * 2;
            wah[g][q] = h01; wah[g][q + 1] = h23;
            wal[g][q] = l01; wal[g][q + 1] = l23;
        }
#pragma unroll
        for (int g = 0; g < 4; g++) {
            uint4 b0 = *(const uint4*)(sbb + (g * 2) * 512 + l * 16);
            mma_bf16(o0, wah[g], b0.x, b0.y);   // Wh·Bh
            mma_bf16(o0, wah[g], b0.z, b0.w);   // Wh·Bl
            mma_bf16(o0, wal[g], b0.x, b0.y);   // Wl·Bh
            uint4 b1 = *(const uint4*)(sbb + (g * 2 + 1) * 512 + l * 16);
            mma_bf16(o1, wah[g], b1.x, b1.y);
            mma_bf16(o1, wah[g], b1.z, b1.w);
            mma_bf16(o1, wal[g], b1.x, b1.y);
        }
    }

    // write out: rows ig + l/4 (+8), cols 2(l&3) (+8 for o1)
    const int r0 = ig + (l >> 2), cb = 2 * (l & 3);
    *(float2*)(out + (size_t)r0 * 16 + cb)            = make_float2(o0[0], o0[1]);
    *(float2*)(out + (size_t)r0 * 16 + 8 + cb)        = make_float2(o1[0], o1[1]);
    *(float2*)(out + (size_t)(r0 + 8) * 16 + cb)      = make_float2(o0[2], o0[3]);
    *(float2*)(out + (size_t)(r0 + 8) * 16 + 8 + cb)  = make_float2(o1[2], o1[3]);
}

extern "C" void kernel_launch(void* const* d_in, const int* in_sizes, int n_in,
                              void* d_out, int out_size) {
    const float* ls = (const float*)d_in[0];
    const float* x  = (const float*)d_in[1];
    const float* y  = (const float*)d_in[2];
    const float* b  = (const float*)d_in[3];
    float* out = (float*)d_out;

    prep_x<<<256, 128>>>(ls, x);
    prep_y<<<512, 128>>>(ls, y);
    prep_b<<<512, 128>>>(b);
    rbf_main<<<256, 128>>>(ls, out);
}

// round 5
// speedup vs baseline: 3.5395x; 1.1757x over previous
#include <cuda_runtime.h>
#include <cuda_bf16.h>
#include <cstdint>

#define LOG2E 1.4426950408889634f
#define NP  16384
#define NT  256      // j-tiles of 64
#define NWG 1024     // i row-groups of 16
#define NSL 3        // j-slices (86/85/85 tiles)

// ---- static device scratch (no allocation) ----
__device__ uint32_t g_Xf[NWG * 32 * 16];  // a-frag image
__device__ uint32_t g_Yf[NT * 2048];      // b-frag image (GEMM1)
__device__ uint32_t g_Bf[NT * 1024];      // b-frag image (GEMM2)
__device__ float g_cxn[NP];
__device__ float g_cyn[NP];
__device__ float g_Op[NSL * NP * 16];     // per-slice fp32 partials (3 MB)

// ---- helpers ----
__device__ __forceinline__ uint32_t smem_u32(const void* p) {
    uint32_t a;
    asm("{ .reg .u64 t; cvta.to.shared.u64 t, %1; cvt.u32.u64 %0, t; }" : "=r"(a) : "l"(p));
    return a;
}
__device__ __forceinline__ void cp16(uint32_t d, const void* s) {
    asm volatile("cp.async.cg.shared.global [%0], [%1], 16;" :: "r"(d), "l"(s));
}
#define CP_COMMIT() asm volatile("cp.async.commit_group;" ::: "memory")
#define CP_WAIT0()  asm volatile("cp.async.wait_group 0;" ::: "memory")

__device__ __forceinline__ void mma_bf16(float* d, const uint32_t* a, uint32_t b0, uint32_t b1) {
    asm volatile("mma.sync.aligned.m16n8k16.row.col.f32.bf16.bf16.f32 "
                 "{%0,%1,%2,%3},{%4,%5,%6,%7},{%8,%9},{%0,%1,%2,%3};"
                 : "+f"(d[0]), "+f"(d[1]), "+f"(d[2]), "+f"(d[3])
                 : "r"(a[0]), "r"(a[1]), "r"(a[2]), "r"(a[3]), "r"(b0), "r"(b1));
}
__device__ __forceinline__ float ex2f(float a) {
    float r; asm("ex2.approx.ftz.f32 %0, %1;" : "=f"(r) : "f"(a)); return r;
}
__device__ __forceinline__ uint32_t pk2(float lo, float hi) {
    __nv_bfloat162 h = __float22bfloat162_rn(make_float2(lo, hi));
    return *(uint32_t*)&h;
}
__device__ __forceinline__ float bflo(uint32_t u) { return __uint_as_float(u << 16); }
__device__ __forceinline__ float bfhi(uint32_t u) { return __uint_as_float(u & 0xffff0000u); }
__device__ __forceinline__ uint32_t pk_split(float a, float b, int low) {
    float ah = __bfloat162float(__float2bfloat16(a));
    float bh = __bfloat162float(__float2bfloat16(b));
    return low ? pk2(a - ah, b - bh) : pk2(ah, bh);
}

// ================= prep kernels (unchanged from R4) =================
__global__ void prep_x(const float* __restrict__ ls, const float* __restrict__ x) {
    int t = blockIdx.x * 128 + threadIdx.x;
    int wg = t >> 5, l = t & 31;
    int r0 = wg * 16 + (l >> 2), r1 = r0 + 8;
    int c = 2 * (l & 3);
    const float* x0 = x + (size_t)r0 * 32;
    const float* x1 = x + (size_t)r1 * 32;
    float v0[8], v1[8], n0 = 0.f, n1 = 0.f;
#pragma unroll
    for (int kf = 0; kf < 2; kf++)
#pragma unroll
        for (int h = 0; h < 2; h++)
#pragma unroll
            for (int e = 0; e < 2; e++) {
                int idx = kf * 4 + h * 2 + e;
                int col = kf * 16 + h * 8 + c + e;
                v0[idx] = x0[col]; v1[idx] = x1[col];
                n0 += v0[idx] * v0[idx];
                n1 += v1[idx] * v1[idx];
            }
    n0 += __shfl_xor_sync(0xffffffffu, n0, 1); n0 += __shfl_xor_sync(0xffffffffu, n0, 2);
    n1 += __shfl_xor_sync(0xffffffffu, n1, 1); n1 += __shfl_xor_sync(0xffffffffu, n1, 2);
    const float cneg = -ls[0] * LOG2E;
    if ((l & 3) == 0) { g_cxn[r0] = cneg * n0; g_cxn[r1] = cneg * n1; }

    uint32_t o[16];
#pragma unroll
    for (int s = 0; s < 2; s++)
#pragma unroll
        for (int kf = 0; kf < 2; kf++)
#pragma unroll
            for (int h = 0; h < 2; h++) {
                o[s * 8 + kf * 4 + h * 2 + 0] = pk_split(v0[kf * 4 + h * 2], v0[kf * 4 + h * 2 + 1], s);
                o[s * 8 + kf * 4 + h * 2 + 1] = pk_split(v1[kf * 4 + h * 2], v1[kf * 4 + h * 2 + 1], s);
            }
    uint4* dst = (uint4*)(g_Xf + (size_t)t * 16);
#pragma unroll
    for (int q = 0; q < 4; q++) dst[q] = make_uint4(o[4 * q], o[4 * q + 1], o[4 * q + 2], o[4 * q + 3]);
}

__global__ void prep_y(const float* __restrict__ ls, const float* __restrict__ y) {
    int t = blockIdx.x * 128 + threadIdx.x;
    int tn = t >> 5, l = t & 31;
    int j = tn * 8 + (l >> 2);
    int c = 2 * (l & 3);
    const float* yr = y + (size_t)j * 32;
    float v[8], n = 0.f;
#pragma unroll
    for (int kf = 0; kf < 2; kf++)
#pragma unroll
        for (int h = 0; h < 2; h++)
#pragma unroll
            for (int e = 0; e < 2; e++) {
                int idx = kf * 4 + h * 2 + e;
                v[idx] = yr[kf * 16 + h * 8 + c + e];
                n += v[idx] * v[idx];
            }
    n += __shfl_xor_sync(0xffffffffu, n, 1); n += __shfl_xor_sync(0xffffffffu, n, 2);
    if ((l & 3) == 0) g_cyn[j] = -ls[0] * LOG2E * n;

    uint32_t o[8];
#pragma unroll
    for (int s = 0; s < 2; s++)
#pragma unroll
        for (int kf = 0; kf < 2; kf++)
#pragma unroll
            for (int h = 0; h < 2; h++)
                o[s * 4 + kf * 2 + h] = pk_split(v[kf * 4 + h * 2], v[kf * 4 + h * 2 + 1], s);
    uint4* dst = (uint4*)(g_Yf + (size_t)tn * 256 + l * 8);
    dst[0] = make_uint4(o[0], o[1], o[2], o[3]);
    dst[1] = make_uint4(o[4], o[5], o[6], o[7]);
}

__global__ void prep_b(const float* __restrict__ b) {
    int t = blockIdx.x * 128 + threadIdx.x;
    int u = t >> 5, l = t & 31;
    int tile = u >> 3, fp = u & 7, kf = fp >> 1, nb2 = fp & 1;
    int c = nb2 * 8 + (l >> 2);
    int jb = tile * 64 + kf * 16 + 2 * (l & 3);
    float p0 = b[(size_t)jb * 16 + c];
    float p1 = b[(size_t)(jb + 1) * 16 + c];
    float p2 = b[(size_t)(jb + 8) * 16 + c];
    float p3 = b[(size_t)(jb + 9) * 16 + c];
    uint32_t h0 = pk_split(p0, p1, 0), h1 = pk_split(p2, p3, 0);
    uint32_t l0 = pk_split(p0, p1, 1), l1 = pk_split(p2, p3, 1);
    *(uint4*)(g_Bf + (size_t)tile * 1024 + fp * 128 + l * 4) = make_uint4(h0, h1, l0, l1);
}

// ================= main kernel =================
#define SMEM_BYTES 25088

__device__ __forceinline__ void issue_loads(uint32_t smb, int tile, int buf, int tid) {
    const char* gy = (const char*)g_Yf + (size_t)tile * 8192;
    uint32_t dy = smb + buf * 8192;
#pragma unroll
    for (int k = 0; k < 4; k++) cp16(dy + (tid + k * 128) * 16, gy + (size_t)(tid + k * 128) * 16);
    const char* gb = (const char*)g_Bf + (size_t)tile * 4096;
    uint32_t db = smb + 16384 + buf * 4096;
#pragma unroll
    for (int k = 0; k < 2; k++) cp16(db + (tid + k * 128) * 16, gb + (size_t)(tid + k * 128) * 16);
    if (tid < 16) cp16(smb + 24576 + buf * 256 + tid * 16, (const char*)(g_cyn + tile * 64) + tid * 16);
}

__global__ void __launch_bounds__(128, 6)
rbf_main(const float* __restrict__ ls) {
    __shared__ __align__(16) char sm[SMEM_BYTES];
    const uint32_t smb = smem_u32(sm);
    const int tid = threadIdx.x, w = tid >> 5, l = tid & 31;
    const int bidx = blockIdx.x;           // i-block 0..255
    const int sl = blockIdx.y;             // j-slice 0..2
    const int tstart = (sl == 0) ? 0 : (86 + 85 * (sl - 1));
    const int tcnt = (sl == 0) ? 86 : 85;
    const int ig = bidx * 64 + w * 16;

    uint32_t xf[16];
    {
        const uint4* p = (const uint4*)(g_Xf + ((size_t)(bidx * 4 + w) * 32 + l) * 16);
#pragma unroll
        for (int q = 0; q < 4; q++) *(uint4*)(xf + 4 * q) = p[q];
    }
    const float cxnA = g_cxn[ig + (l >> 2)];
    const float cxnB = g_cxn[ig + (l >> 2) + 8];
    const float C2 = 2.f * __ldg(ls) * LOG2E;

    float o0[4] = {0.f, 0.f, 0.f, 0.f}, o1[4] = {0.f, 0.f, 0.f, 0.f};

    issue_loads(smb, tstart, 0, tid);
    CP_COMMIT();

    for (int tt = 0; tt < tcnt; tt++) {
        CP_WAIT0();
        __syncthreads();
        if (tt + 1 < tcnt) { issue_loads(smb, tstart + tt + 1, (tt + 1) & 1, tid); CP_COMMIT(); }
        const int buf = tt & 1;
        const char* syb = sm + buf * 8192;
        const char* sbb = sm + 16384 + buf * 4096;
        const char* scy = sm + 24576 + buf * 256;

#pragma unroll
        for (int g = 0; g < 4; g++) {
            uint32_t wah[4], wal[4];
#pragma unroll
            for (int h = 0; h < 2; h++) {
                const int nb = g * 2 + h;
                uint4 y0 = *(const uint4*)(syb + nb * 1024 + l * 32);
                uint4 y1 = *(const uint4*)(syb + nb * 1024 + l * 32 + 16);
                float s[4] = {0.f, 0.f, 0.f, 0.f};
                mma_bf16(s, xf + 0,  y0.x, y0.y);   // Xh kf0 · Yh kf0
                mma_bf16(s, xf + 4,  y0.z, y0.w);   // Xh kf1 · Yh kf1
                mma_bf16(s, xf + 0,  y1.x, y1.y);   // Xh kf0 · Yl kf0
                mma_bf16(s, xf + 4,  y1.z, y1.w);   // Xh kf1 · Yl kf1
                mma_bf16(s, xf + 8,  y0.x, y0.y);   // Xl kf0 · Yh kf0
                mma_bf16(s, xf + 12, y0.z, y0.w);   // Xl kf1 · Yh kf1

                float2 cy = *(const float2*)(scy + nb * 32 + (l & 3) * 8);
                float w0 = ex2f(fminf(fmaf(C2, s[0], cxnA + cy.x), 0.f));
                float w1 = ex2f(fminf(fmaf(C2, s[1], cxnA + cy.y), 0.f));
                float w2 = ex2f(fminf(fmaf(C2, s[2], cxnB + cy.x), 0.f));
                float w3 = ex2f(fminf(fmaf(C2, s[3], cxnB + cy.y), 0.f));
                uint32_t h01 = pk2(w0, w1), h23 = pk2(w2, w3);
                wah[h * 2] = h01; wah[h * 2 + 1] = h23;
                wal[h * 2] = pk2(w0 - bflo(h01), w1 - bfhi(h01));
                wal[h * 2 + 1] = pk2(w2 - bflo(h23), w3 - bfhi(h23));
            }
            // GEMM2 for this g-group (same MMA order into o0/o1 as R4)
            uint4 b0 = *(const uint4*)(sbb + (g * 2) * 512 + l * 16);
            mma_bf16(o0, wah, b0.x, b0.y);   // Wh·Bh
            mma_bf16(o0, wah, b0.z, b0.w);   // Wh·Bl
            mma_bf16(o0, wal, b0.x, b0.y);   // Wl·Bh
            uint4 b1 = *(const uint4*)(sbb + (g * 2 + 1) * 512 + l * 16);
            mma_bf16(o1, wah, b1.x, b1.y);
            mma_bf16(o1, wah, b1.z, b1.w);
            mma_bf16(o1, wal, b1.x, b1.y);
        }
    }

    // partial write: slice-local buffer
    float* op = g_Op + (size_t)sl * (NP * 16);
    const int r0 = ig + (l >> 2), cb = 2 * (l & 3);
    *(float2*)(op + (size_t)r0 * 16 + cb)           = make_float2(o0[0], o0[1]);
    *(float2*)(op + (size_t)r0 * 16 + 8 + cb)       = make_float2(o1[0], o1[1]);
    *(float2*)(op + (size_t)(r0 + 8) * 16 + cb)     = make_float2(o0[2], o0[3]);
    *(float2*)(op + (size_t)(r0 + 8) * 16 + 8 + cb) = make_float2(o1[2], o1[3]);
}

// ================= deterministic slice reduction =================
__global__ void reduce_k(float* __restrict__ out) {
    int idx = blockIdx.x * 256 + threadIdx.x;  // one float4 each, 65536 threads
    float4 a = ((const float4*)g_Op)[idx];
    float4 b = ((const float4*)(g_Op + NP * 16))[idx];
    float4 c = ((const float4*)(g_Op + 2 * NP * 16))[idx];
    float4 o;
    o.x = (a.x + b.x) + c.x;
    o.y = (a.y + b.y) + c.y;
    o.z = (a.z + b.z) + c.z;
    o.w = (a.w + b.w) + c.w;
    ((float4*)out)[idx] = o;
}

extern "C" void kernel_launch(void* const* d_in, const int* in_sizes, int n_in,
                              void* d_out, int out_size) {
    const float* ls = (const float*)d_in[0];
    const float* x  = (const float*)d_in[1];
    const float* y  = (const float*)d_in[2];
    const float* b  = (const float*)d_in[3];
    float* out = (float*)d_out;

    prep_x<<<256, 128>>>(ls, x);
    prep_y<<<512, 128>>>(ls, y);
    prep_b<<<512, 128>>>(b);
    rbf_main<<<dim3(256, NSL), 128>>>(ls);
    reduce_k<<<256, 256>>>(out);
}

// round 6
// speedup vs baseline: 3.9461x; 1.1149x over previous
#include <cuda_runtime.h>
#include <cuda_bf16.h>
#include <cstdint>

#define LOG2E 1.4426950408889634f
#define NP  16384
#define NT  256      // j-tiles of 64
#define NWG 1024     // i row-groups of 16
#define NSL 6        // j-slices (43,43,43,43,42,42)

// ---- static device scratch (no allocation) ----
__device__ uint32_t g_Xf[NWG * 32 * 16];  // a-frag image
__device__ uint32_t g_Yf[NT * 2048];      // b-frag image (GEMM1)
__device__ uint32_t g_Bf[NT * 1024];      // b-frag image (GEMM2)
__device__ float g_cxn[NP];
__device__ float g_cyn[NP];
__device__ float g_Op[NSL * NP * 16];     // per-slice fp32 partials (6 MB)

// ---- helpers ----
__device__ __forceinline__ uint32_t smem_u32(const void* p) {
    uint32_t a;
    asm("{ .reg .u64 t; cvta.to.shared.u64 t, %1; cvt.u32.u64 %0, t; }" : "=r"(a) : "l"(p));
    return a;
}
__device__ __forceinline__ void cp16(uint32_t d, const void* s) {
    asm volatile("cp.async.cg.shared.global [%0], [%1], 16;" :: "r"(d), "l"(s));
}
#define CP_COMMIT() asm volatile("cp.async.commit_group;" ::: "memory")
#define CP_WAIT0()  asm volatile("cp.async.wait_group 0;" ::: "memory")

__device__ __forceinline__ void mma_bf16(float* d, const uint32_t* a, uint32_t b0, uint32_t b1) {
    asm volatile("mma.sync.aligned.m16n8k16.row.col.f32.bf16.bf16.f32 "
                 "{%0,%1,%2,%3},{%4,%5,%6,%7},{%8,%9},{%0,%1,%2,%3};"
                 : "+f"(d[0]), "+f"(d[1]), "+f"(d[2]), "+f"(d[3])
                 : "r"(a[0]), "r"(a[1]), "r"(a[2]), "r"(a[3]), "r"(b0), "r"(b1));
}
__device__ __forceinline__ float ex2f(float a) {
    float r; asm("ex2.approx.ftz.f32 %0, %1;" : "=f"(r) : "f"(a)); return r;
}
__device__ __forceinline__ uint32_t pk2(float lo, float hi) {
    __nv_bfloat162 h = __float22bfloat162_rn(make_float2(lo, hi));
    return *(uint32_t*)&h;
}
__device__ __forceinline__ float bflo(uint32_t u) { return __uint_as_float(u << 16); }
__device__ __forceinline__ float bfhi(uint32_t u) { return __uint_as_float(u & 0xffff0000u); }
__device__ __forceinline__ uint32_t pk_split(float a, float b, int low) {
    float ah = __bfloat162float(__float2bfloat16(a));
    float bh = __bfloat162float(__float2bfloat16(b));
    return low ? pk2(a - ah, b - bh) : pk2(ah, bh);
}

// ================= prep kernels (unchanged) =================
__global__ void prep_x(const float* __restrict__ ls, const float* __restrict__ x) {
    int t = blockIdx.x * 128 + threadIdx.x;
    int wg = t >> 5, l = t & 31;
    int r0 = wg * 16 + (l >> 2), r1 = r0 + 8;
    int c = 2 * (l & 3);
    const float* x0 = x + (size_t)r0 * 32;
    const float* x1 = x + (size_t)r1 * 32;
    float v0[8], v1[8], n0 = 0.f, n1 = 0.f;
#pragma unroll
    for (int kf = 0; kf < 2; kf++)
#pragma unroll
        for (int h = 0; h < 2; h++)
#pragma unroll
            for (int e = 0; e < 2; e++) {
                int idx = kf * 4 + h * 2 + e;
                int col = kf * 16 + h * 8 + c + e;
                v0[idx] = x0[col]; v1[idx] = x1[col];
                n0 += v0[idx] * v0[idx];
                n1 += v1[idx] * v1[idx];
            }
    n0 += __shfl_xor_sync(0xffffffffu, n0, 1); n0 += __shfl_xor_sync(0xffffffffu, n0, 2);
    n1 += __shfl_xor_sync(0xffffffffu, n1, 1); n1 += __shfl_xor_sync(0xffffffffu, n1, 2);
    const float cneg = -ls[0] * LOG2E;
    if ((l & 3) == 0) { g_cxn[r0] = cneg * n0; g_cxn[r1] = cneg * n1; }

    uint32_t o[16];
#pragma unroll
    for (int s = 0; s < 2; s++)
#pragma unroll
        for (int kf = 0; kf < 2; kf++)
#pragma unroll
            for (int h = 0; h < 2; h++) {
                o[s * 8 + kf * 4 + h * 2 + 0] = pk_split(v0[kf * 4 + h * 2], v0[kf * 4 + h * 2 + 1], s);
                o[s * 8 + kf * 4 + h * 2 + 1] = pk_split(v1[kf * 4 + h * 2], v1[kf * 4 + h * 2 + 1], s);
            }
    uint4* dst = (uint4*)(g_Xf + (size_t)t * 16);
#pragma unroll
    for (int q = 0; q < 4; q++) dst[q] = make_uint4(o[4 * q], o[4 * q + 1], o[4 * q + 2], o[4 * q + 3]);
}

__global__ void prep_y(const float* __restrict__ ls, const float* __restrict__ y) {
    int t = blockIdx.x * 128 + threadIdx.x;
    int tn = t >> 5, l = t & 31;
    int j = tn * 8 + (l >> 2);
    int c = 2 * (l & 3);
    const float* yr = y + (size_t)j * 32;
    float v[8], n = 0.f;
#pragma unroll
    for (int kf = 0; kf < 2; kf++)
#pragma unroll
        for (int h = 0; h < 2; h++)
#pragma unroll
            for (int e = 0; e < 2; e++) {
                int idx = kf * 4 + h * 2 + e;
                v[idx] = yr[kf * 16 + h * 8 + c + e];
                n += v[idx] * v[idx];
            }
    n += __shfl_xor_sync(0xffffffffu, n, 1); n += __shfl_xor_sync(0xffffffffu, n, 2);
    if ((l & 3) == 0) g_cyn[j] = -ls[0] * LOG2E * n;

    uint32_t o[8];
#pragma unroll
    for (int s = 0; s < 2; s++)
#pragma unroll
        for (int kf = 0; kf < 2; kf++)
#pragma unroll
            for (int h = 0; h < 2; h++)
                o[s * 4 + kf * 2 + h] = pk_split(v[kf * 4 + h * 2], v[kf * 4 + h * 2 + 1], s);
    uint4* dst = (uint4*)(g_Yf + (size_t)tn * 256 + l * 8);
    dst[0] = make_uint4(o[0], o[1], o[2], o[3]);
    dst[1] = make_uint4(o[4], o[5], o[6], o[7]);
}

__global__ void prep_b(const float* __restrict__ b) {
    int t = blockIdx.x * 128 + threadIdx.x;
    int u = t >> 5, l = t & 31;
    int tile = u >> 3, fp = u & 7, kf = fp >> 1, nb2 = fp & 1;
    int c = nb2 * 8 + (l >> 2);
    int jb = tile * 64 + kf * 16 + 2 * (l & 3);
    float p0 = b[(size_t)jb * 16 + c];
    float p1 = b[(size_t)(jb + 1) * 16 + c];
    float p2 = b[(size_t)(jb + 8) * 16 + c];
    float p3 = b[(size_t)(jb + 9) * 16 + c];
    uint32_t h0 = pk_split(p0, p1, 0), h1 = pk_split(p2, p3, 0);
    uint32_t l0 = pk_split(p0, p1, 1), l1 = pk_split(p2, p3, 1);
    *(uint4*)(g_Bf + (size_t)tile * 1024 + fp * 128 + l * 4) = make_uint4(h0, h1, l0, l1);
}

// ================= main kernel =================
#define SMEM_BYTES 25088

__device__ __forceinline__ void issue_loads(uint32_t smb, int tile, int buf, int tid) {
    const char* gy = (const char*)g_Yf + (size_t)tile * 8192;
    uint32_t dy = smb + buf * 8192;
#pragma unroll
    for (int k = 0; k < 4; k++) cp16(dy + (tid + k * 128) * 16, gy + (size_t)(tid + k * 128) * 16);
    const char* gb = (const char*)g_Bf + (size_t)tile * 4096;
    uint32_t db = smb + 16384 + buf * 4096;
#pragma unroll
    for (int k = 0; k < 2; k++) cp16(db + (tid + k * 128) * 16, gb + (size_t)(tid + k * 128) * 16);
    if (tid < 16) cp16(smb + 24576 + buf * 256 + tid * 16, (const char*)(g_cyn + tile * 64) + tid * 16);
}

__global__ void __launch_bounds__(128, 6)
rbf_main(const float* __restrict__ ls) {
    __shared__ __align__(16) char sm[SMEM_BYTES];
    const uint32_t smb = smem_u32(sm);
    const int tid = threadIdx.x, w = tid >> 5, l = tid & 31;
    const int bidx = blockIdx.x;           // i-block 0..255
    const int sl = blockIdx.y;             // j-slice 0..5
    const int tstart = (sl < 4) ? 43 * sl : (172 + 42 * (sl - 4));
    const int tcnt = (sl < 4) ? 43 : 42;
    const int ig = bidx * 64 + w * 16;

    uint32_t xf[16];
    {
        const uint4* p = (const uint4*)(g_Xf + ((size_t)(bidx * 4 + w) * 32 + l) * 16);
#pragma unroll
        for (int q = 0; q < 4; q++) *(uint4*)(xf + 4 * q) = p[q];
    }
    const float cxnA = g_cxn[ig + (l >> 2)];
    const float cxnB = g_cxn[ig + (l >> 2) + 8];
    const float C2 = 2.f * __ldg(ls) * LOG2E;

    float o0[4] = {0.f, 0.f, 0.f, 0.f}, o1[4] = {0.f, 0.f, 0.f, 0.f};

    issue_loads(smb, tstart, 0, tid);
    CP_COMMIT();

    for (int tt = 0; tt < tcnt; tt++) {
        CP_WAIT0();
        __syncthreads();
        if (tt + 1 < tcnt) { issue_loads(smb, tstart + tt + 1, (tt + 1) & 1, tid); CP_COMMIT(); }
        const int buf = tt & 1;
        const char* syb = sm + buf * 8192;
        const char* sbb = sm + 16384 + buf * 4096;
        const char* scy = sm + 24576 + buf * 256;

#pragma unroll
        for (int g = 0; g < 4; g++) {
            uint32_t wah[4], wal[4];
#pragma unroll
            for (int h = 0; h < 2; h++) {
                const int nb = g * 2 + h;
                uint4 y0 = *(const uint4*)(syb + nb * 1024 + l * 32);
                uint4 y1 = *(const uint4*)(syb + nb * 1024 + l * 32 + 16);
                float s[4] = {0.f, 0.f, 0.f, 0.f};
                mma_bf16(s, xf + 0,  y0.x, y0.y);   // Xh kf0 · Yh kf0
                mma_bf16(s, xf + 4,  y0.z, y0.w);   // Xh kf1 · Yh kf1
                mma_bf16(s, xf + 0,  y1.x, y1.y);   // Xh kf0 · Yl kf0
                mma_bf16(s, xf + 4,  y1.z, y1.w);   // Xh kf1 · Yl kf1
                mma_bf16(s, xf + 8,  y0.x, y0.y);   // Xl kf0 · Yh kf0
                mma_bf16(s, xf + 12, y0.z, y0.w);   // Xl kf1 · Yh kf1

                float2 cy = *(const float2*)(scy + nb * 32 + (l & 3) * 8);
                float w0 = ex2f(fminf(fmaf(C2, s[0], cxnA + cy.x), 0.f));
                float w1 = ex2f(fminf(fmaf(C2, s[1], cxnA + cy.y), 0.f));
                float w2 = ex2f(fminf(fmaf(C2, s[2], cxnB + cy.x), 0.f));
                float w3 = ex2f(fminf(fmaf(C2, s[3], cxnB + cy.y), 0.f));
                uint32_t h01 = pk2(w0, w1), h23 = pk2(w2, w3);
                wah[h * 2] = h01; wah[h * 2 + 1] = h23;
                wal[h * 2] = pk2(w0 - bflo(h01), w1 - bfhi(h01));
                wal[h * 2 + 1] = pk2(w2 - bflo(h23), w3 - bfhi(h23));
            }
            // GEMM2 for this g-group (same MMA order into o0/o1)
            uint4 b0 = *(const uint4*)(sbb + (g * 2) * 512 + l * 16);
            mma_bf16(o0, wah, b0.x, b0.y);   // Wh·Bh
            mma_bf16(o0, wah, b0.z, b0.w);   // Wh·Bl
            mma_bf16(o0, wal, b0.x, b0.y);   // Wl·Bh
            uint4 b1 = *(const uint4*)(sbb + (g * 2 + 1) * 512 + l * 16);
            mma_bf16(o1, wah, b1.x, b1.y);
            mma_bf16(o1, wah, b1.z, b1.w);
            mma_bf16(o1, wal, b1.x, b1.y);
        }
    }

    // partial write: slice-local buffer
    float* op = g_Op + (size_t)sl * (NP * 16);
    const int r0 = ig + (l >> 2), cb = 2 * (l & 3);
    *(float2*)(op + (size_t)r0 * 16 + cb)           = make_float2(o0[0], o0[1]);
    *(float2*)(op + (size_t)r0 * 16 + 8 + cb)       = make_float2(o1[0], o1[1]);
    *(float2*)(op + (size_t)(r0 + 8) * 16 + cb)     = make_float2(o0[2], o0[3]);
    *(float2*)(op + (size_t)(r0 + 8) * 16 + 8 + cb) = make_float2(o1[2], o1[3]);
}

// ================= deterministic slice reduction =================
__global__ void reduce_k(float* __restrict__ out) {
    int idx = blockIdx.x * 256 + threadIdx.x;  // one float4 each, 65536 threads
    float4 o = ((const float4*)g_Op)[idx];
#pragma unroll
    for (int s = 1; s < NSL; s++) {
        float4 v = ((const float4*)(g_Op + (size_t)s * NP * 16))[idx];
        o.x += v.x; o.y += v.y; o.z += v.z; o.w += v.w;   // fixed slice order
    }
    ((float4*)out)[idx] = o;
}

extern "C" void kernel_launch(void* const* d_in, const int* in_sizes, int n_in,
                              void* d_out, int out_size) {
    const float* ls = (const float*)d_in[0];
    const float* x  = (const float*)d_in[1];
    const float* y  = (const float*)d_in[2];
    const float* b  = (const float*)d_in[3];
    float* out = (float*)d_out;

    prep_x<<<256, 128>>>(ls, x);
    prep_y<<<512, 128>>>(ls, y);
    prep_b<<<512, 128>>>(b);
    rbf_main<<<dim3(256, NSL), 128>>>(ls);
    reduce_k<<<256, 256>>>(out);
}

// round 7
// speedup vs baseline: 3.9516x; 1.0014x over previous
#include <cuda_runtime.h>
#include <cuda_bf16.h>
#include <cstdint>

#define LOG2E 1.4426950408889634f
#define NP  16384
#define NT  256      // j-tiles of 64
#define NWG 1024     // i row-groups of 16
#define NSL 6        // j-slices (43,43,43,43,42,42)

// ---- static device scratch (no allocation) ----
__device__ uint32_t g_Xf[NWG * 32 * 16];  // a-frag image
__device__ uint32_t g_Yf[NT * 2048];      // b-frag image (GEMM1)
__device__ uint32_t g_Bf[NT * 1024];      // b-frag image (GEMM2)
__device__ float g_cxn[NP];
__device__ float g_cyn[NP];
__device__ float g_Op[NSL * NP * 16];     // per-slice fp32 partials (6 MB)

// ---- helpers ----
__device__ __forceinline__ uint32_t smem_u32(const void* p) {
    uint32_t a;
    asm("{ .reg .u64 t; cvta.to.shared.u64 t, %1; cvt.u32.u64 %0, t; }" : "=r"(a) : "l"(p));
    return a;
}
__device__ __forceinline__ void cp16(uint32_t d, const void* s) {
    asm volatile("cp.async.cg.shared.global [%0], [%1], 16;" :: "r"(d), "l"(s));
}
#define CP_COMMIT() asm volatile("cp.async.commit_group;" ::: "memory")
#define CP_WAIT0()  asm volatile("cp.async.wait_group 0;" ::: "memory")

__device__ __forceinline__ void mma_bf16(float* d, const uint32_t* a, uint32_t b0, uint32_t b1) {
    asm volatile("mma.sync.aligned.m16n8k16.row.col.f32.bf16.bf16.f32 "
                 "{%0,%1,%2,%3},{%4,%5,%6,%7},{%8,%9},{%0,%1,%2,%3};"
                 : "+f"(d[0]), "+f"(d[1]), "+f"(d[2]), "+f"(d[3])
                 : "r"(a[0]), "r"(a[1]), "r"(a[2]), "r"(a[3]), "r"(b0), "r"(b1));
}
__device__ __forceinline__ float ex2f(float a) {
    float r; asm("ex2.approx.ftz.f32 %0, %1;" : "=f"(r) : "f"(a)); return r;
}
__device__ __forceinline__ uint32_t pk2(float lo, float hi) {
    __nv_bfloat162 h = __float22bfloat162_rn(make_float2(lo, hi));
    return *(uint32_t*)&h;
}
__device__ __forceinline__ float bflo(uint32_t u) { return __uint_as_float(u << 16); }
__device__ __forceinline__ float bfhi(uint32_t u) { return __uint_as_float(u & 0xffff0000u); }
__device__ __forceinline__ uint32_t pk_split(float a, float b, int low) {
    float ah = __bfloat162float(__float2bfloat16(a));
    float bh = __bfloat162float(__float2bfloat16(b));
    return low ? pk2(a - ah, b - bh) : pk2(ah, bh);
}

// ================= prep kernels (unchanged) =================
__global__ void prep_x(const float* __restrict__ ls, const float* __restrict__ x) {
    int t = blockIdx.x * 128 + threadIdx.x;
    int wg = t >> 5, l = t & 31;
    int r0 = wg * 16 + (l >> 2), r1 = r0 + 8;
    int c = 2 * (l & 3);
    const float* x0 = x + (size_t)r0 * 32;
    const float* x1 = x + (size_t)r1 * 32;
    float v0[8], v1[8], n0 = 0.f, n1 = 0.f;
#pragma unroll
    for (int kf = 0; kf < 2; kf++)
#pragma unroll
        for (int h = 0; h < 2; h++)
#pragma unroll
            for (int e = 0; e < 2; e++) {
                int idx = kf * 4 + h * 2 + e;
                int col = kf * 16 + h * 8 + c + e;
                v0[idx] = x0[col]; v1[idx] = x1[col];
                n0 += v0[idx] * v0[idx];
                n1 += v1[idx] * v1[idx];
            }
    n0 += __shfl_xor_sync(0xffffffffu, n0, 1); n0 += __shfl_xor_sync(0xffffffffu, n0, 2);
    n1 += __shfl_xor_sync(0xffffffffu, n1, 1); n1 += __shfl_xor_sync(0xffffffffu, n1, 2);
    const float cneg = -ls[0] * LOG2E;
    if ((l & 3) == 0) { g_cxn[r0] = cneg * n0; g_cxn[r1] = cneg * n1; }

    uint32_t o[16];
#pragma unroll
    for (int s = 0; s < 2; s++)
#pragma unroll
        for (int kf = 0; kf < 2; kf++)
#pragma unroll
            for (int h = 0; h < 2; h++) {
                o[s * 8 + kf * 4 + h * 2 + 0] = pk_split(v0[kf * 4 + h * 2], v0[kf * 4 + h * 2 + 1], s);
                o[s * 8 + kf * 4 + h * 2 + 1] = pk_split(v1[kf * 4 + h * 2], v1[kf * 4 + h * 2 + 1], s);
            }
    uint4* dst = (uint4*)(g_Xf + (size_t)t * 16);
#pragma unroll
    for (int q = 0; q < 4; q++) dst[q] = make_uint4(o[4 * q], o[4 * q + 1], o[4 * q + 2], o[4 * q + 3]);
}

__global__ void prep_y(const float* __restrict__ ls, const float* __restrict__ y) {
    int t = blockIdx.x * 128 + threadIdx.x;
    int tn = t >> 5, l = t & 31;
    int j = tn * 8 + (l >> 2);
    int c = 2 * (l & 3);
    const float* yr = y + (size_t)j * 32;
    float v[8], n = 0.f;
#pragma unroll
    for (int kf = 0; kf < 2; kf++)
#pragma unroll
        for (int h = 0; h < 2; h++)
#pragma unroll
            for (int e = 0; e < 2; e++) {
                int idx = kf * 4 + h * 2 + e;
                v[idx] = yr[kf * 16 + h * 8 + c + e];
                n += v[idx] * v[idx];
            }
    n += __shfl_xor_sync(0xffffffffu, n, 1); n += __shfl_xor_sync(0xffffffffu, n, 2);
    if ((l & 3) == 0) g_cyn[j] = -ls[0] * LOG2E * n;

    uint32_t o[8];
#pragma unroll
    for (int s = 0; s < 2; s++)
#pragma unroll
        for (int kf = 0; kf < 2; kf++)
#pragma unroll
            for (int h = 0; h < 2; h++)
                o[s * 4 + kf * 2 + h] = pk_split(v[kf * 4 + h * 2], v[kf * 4 + h * 2 + 1], s);
    uint4* dst = (uint4*)(g_Yf + (size_t)tn * 256 + l * 8);
    dst[0] = make_uint4(o[0], o[1], o[2], o[3]);
    dst[1] = make_uint4(o[4], o[5], o[6], o[7]);
}

__global__ void prep_b(const float* __restrict__ b) {
    int t = blockIdx.x * 128 + threadIdx.x;
    int u = t >> 5, l = t & 31;
    int tile = u >> 3, fp = u & 7, kf = fp >> 1, nb2 = fp & 1;
    int c = nb2 * 8 + (l >> 2);
    int jb = tile * 64 + kf * 16 + 2 * (l & 3);
    float p0 = b[(size_t)jb * 16 + c];
    float p1 = b[(size_t)(jb + 1) * 16 + c];
    float p2 = b[(size_t)(jb + 8) * 16 + c];
    float p3 = b[(size_t)(jb + 9) * 16 + c];
    uint32_t h0 = pk_split(p0, p1, 0), h1 = pk_split(p2, p3, 0);
    uint32_t l0 = pk_split(p0, p1, 1), l1 = pk_split(p2, p3, 1);
    *(uint4*)(g_Bf + (size_t)tile * 1024 + fp * 128 + l * 4) = make_uint4(h0, h1, l0, l1);
}

// ================= main kernel: 4 warps x 32 i-rows = 128 i-rows/CTA =================
#define SMEM_BYTES 25088

__device__ __forceinline__ void issue_loads(uint32_t smb, int tile, int buf, int tid) {
    const char* gy = (const char*)g_Yf + (size_t)tile * 8192;
    uint32_t dy = smb + buf * 8192;
#pragma unroll
    for (int k = 0; k < 4; k++) cp16(dy + (tid + k * 128) * 16, gy + (size_t)(tid + k * 128) * 16);
    const char* gb = (const char*)g_Bf + (size_t)tile * 4096;
    uint32_t db = smb + 16384 + buf * 4096;
#pragma unroll
    for (int k = 0; k < 2; k++) cp16(db + (tid + k * 128) * 16, gb + (size_t)(tid + k * 128) * 16);
    if (tid < 16) cp16(smb + 24576 + buf * 256 + tid * 16, (const char*)(g_cyn + tile * 64) + tid * 16);
}

__global__ void __launch_bounds__(128, 4)
rbf_main(const float* __restrict__ ls) {
    __shared__ __align__(16) char sm[SMEM_BYTES];
    const uint32_t smb = smem_u32(sm);
    const int tid = threadIdx.x, w = tid >> 5, l = tid & 31;
    const int bidx = blockIdx.x;           // i-block 0..127 (128 rows each)
    const int sl = blockIdx.y;             // j-slice 0..5
    const int tstart = (sl < 4) ? 43 * sl : (172 + 42 * (sl - 4));
    const int tcnt = (sl < 4) ? 43 : 42;
    const int ig = bidx * 128 + w * 32;    // first i-row of this warp's 32

    // two persistent a-frag sets: half A = rows ig..ig+15, half B = ig+16..ig+31
    uint32_t xfA[16], xfB[16];
    {
        const uint4* pA = (const uint4*)(g_Xf + ((size_t)(bidx * 8 + 2 * w) * 32 + l) * 16);
        const uint4* pB = (const uint4*)(g_Xf + ((size_t)(bidx * 8 + 2 * w + 1) * 32 + l) * 16);
#pragma unroll
        for (int q = 0; q < 4; q++) { *(uint4*)(xfA + 4 * q) = pA[q]; *(uint4*)(xfB + 4 * q) = pB[q]; }
    }
    const float cxnA0 = g_cxn[ig + (l >> 2)];
    const float cxnA1 = g_cxn[ig + (l >> 2) + 8];
    const float cxnB0 = g_cxn[ig + (l >> 2) + 16];
    const float cxnB1 = g_cxn[ig + (l >> 2) + 24];
    const float C2 = 2.f * __ldg(ls) * LOG2E;

    float o0A[4] = {0.f, 0.f, 0.f, 0.f}, o1A[4] = {0.f, 0.f, 0.f, 0.f};
    float o0B[4] = {0.f, 0.f, 0.f, 0.f}, o1B[4] = {0.f, 0.f, 0.f, 0.f};

    issue_loads(smb, tstart, 0, tid);
    CP_COMMIT();

    for (int tt = 0; tt < tcnt; tt++) {
        CP_WAIT0();
        __syncthreads();
        if (tt + 1 < tcnt) { issue_loads(smb, tstart + tt + 1, (tt + 1) & 1, tid); CP_COMMIT(); }
        const int buf = tt & 1;
        const char* syb = sm + buf * 8192;
        const char* sbb = sm + 16384 + buf * 4096;
        const char* scy = sm + 24576 + buf * 256;

#pragma unroll
        for (int g = 0; g < 4; g++) {
            uint32_t wahA[4], walA[4], wahB[4], walB[4];
#pragma unroll
            for (int h = 0; h < 2; h++) {
                const int nb = g * 2 + h;
                uint4 y0 = *(const uint4*)(syb + nb * 1024 + l * 32);
                uint4 y1 = *(const uint4*)(syb + nb * 1024 + l * 32 + 16);
                float sA[4] = {0.f, 0.f, 0.f, 0.f}, sB[4] = {0.f, 0.f, 0.f, 0.f};
                mma_bf16(sA, xfA + 0,  y0.x, y0.y);
                mma_bf16(sB, xfB + 0,  y0.x, y0.y);
                mma_bf16(sA, xfA + 4,  y0.z, y0.w);
                mma_bf16(sB, xfB + 4,  y0.z, y0.w);
                mma_bf16(sA, xfA + 0,  y1.x, y1.y);
                mma_bf16(sB, xfB + 0,  y1.x, y1.y);
                mma_bf16(sA, xfA + 4,  y1.z, y1.w);
                mma_bf16(sB, xfB + 4,  y1.z, y1.w);
                mma_bf16(sA, xfA + 8,  y0.x, y0.y);
                mma_bf16(sB, xfB + 8,  y0.x, y0.y);
                mma_bf16(sA, xfA + 12, y0.z, y0.w);
                mma_bf16(sB, xfB + 12, y0.z, y0.w);

                float2 cy = *(const float2*)(scy + nb * 32 + (l & 3) * 8);
                // half A epilogue
                {
                    float w0 = ex2f(fminf(fmaf(C2, sA[0], cxnA0 + cy.x), 0.f));
                    float w1 = ex2f(fminf(fmaf(C2, sA[1], cxnA0 + cy.y), 0.f));
                    float w2 = ex2f(fminf(fmaf(C2, sA[2], cxnA1 + cy.x), 0.f));
                    float w3 = ex2f(fminf(fmaf(C2, sA[3], cxnA1 + cy.y), 0.f));
                    uint32_t h01 = pk2(w0, w1), h23 = pk2(w2, w3);
                    wahA[h * 2] = h01; wahA[h * 2 + 1] = h23;
                    walA[h * 2] = pk2(w0 - bflo(h01), w1 - bfhi(h01));
                    walA[h * 2 + 1] = pk2(w2 - bflo(h23), w3 - bfhi(h23));
                }
                // half B epilogue
                {
                    float w0 = ex2f(fminf(fmaf(C2, sB[0], cxnB0 + cy.x), 0.f));
                    float w1 = ex2f(fminf(fmaf(C2, sB[1], cxnB0 + cy.y), 0.f));
                    float w2 = ex2f(fminf(fmaf(C2, sB[2], cxnB1 + cy.x), 0.f));
                    float w3 = ex2f(fminf(fmaf(C2, sB[3], cxnB1 + cy.y), 0.f));
                    uint32_t h01 = pk2(w0, w1), h23 = pk2(w2, w3);
                    wahB[h * 2] = h01; wahB[h * 2 + 1] = h23;
                    walB[h * 2] = pk2(w0 - bflo(h01), w1 - bfhi(h01));
                    walB[h * 2 + 1] = pk2(w2 - bflo(h23), w3 - bfhi(h23));
                }
            }
            // GEMM2 for this g-group; b0/b1 register loads shared by both halves
            uint4 b0 = *(const uint4*)(sbb + (g * 2) * 512 + l * 16);
            mma_bf16(o0A, wahA, b0.x, b0.y);
            mma_bf16(o0B, wahB, b0.x, b0.y);
            mma_bf16(o0A, wahA, b0.z, b0.w);
            mma_bf16(o0B, wahB, b0.z, b0.w);
            mma_bf16(o0A, walA, b0.x, b0.y);
            mma_bf16(o0B, walB, b0.x, b0.y);
            uint4 b1 = *(const uint4*)(sbb + (g * 2 + 1) * 512 + l * 16);
            mma_bf16(o1A, wahA, b1.x, b1.y);
            mma_bf16(o1B, wahB, b1.x, b1.y);
            mma_bf16(o1A, wahA, b1.z, b1.w);
            mma_bf16(o1B, wahB, b1.z, b1.w);
            mma_bf16(o1A, walA, b1.x, b1.y);
            mma_bf16(o1B, walB, b1.x, b1.y);
        }
    }

    // partial write: slice-local buffer
    float* op = g_Op + (size_t)sl * (NP * 16);
    const int cb = 2 * (l & 3);
    const int rA = ig + (l >> 2), rB = rA + 16;
    *(float2*)(op + (size_t)rA * 16 + cb)            = make_float2(o0A[0], o0A[1]);
    *(float2*)(op + (size_t)rA * 16 + 8 + cb)        = make_float2(o1A[0], o1A[1]);
    *(float2*)(op + (size_t)(rA + 8) * 16 + cb)      = make_float2(o0A[2], o0A[3]);
    *(float2*)(op + (size_t)(rA + 8) * 16 + 8 + cb)  = make_float2(o1A[2], o1A[3]);
    *(float2*)(op + (size_t)rB * 16 + cb)            = make_float2(o0B[0], o0B[1]);
    *(float2*)(op + (size_t)rB * 16 + 8 + cb)        = make_float2(o1B[0], o1B[1]);
    *(float2*)(op + (size_t)(rB + 8) * 16 + cb)      = make_float2(o0B[2], o0B[3]);
    *(float2*)(op + (size_t)(rB + 8) * 16 + 8 + cb)  = make_float2(o1B[2], o1B[3]);
}

// ================= deterministic slice reduction =================
__global__ void reduce_k(float* __restrict__ out) {
    int idx = blockIdx.x * 256 + threadIdx.x;
    float4 o = ((const float4*)g_Op)[idx];
#pragma unroll
    for (int s = 1; s < NSL; s++) {
        float4 v = ((const float4*)(g_Op + (size_t)s * NP * 16))[idx];
        o.x += v.x; o.y += v.y; o.z += v.z; o.w += v.w;   // fixed slice order
    }
    ((float4*)out)[idx] = o;
}

extern "C" void kernel_launch(void* const* d_in, const int* in_sizes, int n_in,
                              void* d_out, int out_size) {
    const float* ls = (const float*)d_in[0];
    const float* x  = (const float*)d_in[1];
    const float* y  = (const float*)d_in[2];
    const float* b  = (const float*)d_in[3];
    float* out = (float*)d_out;

    prep_x<<<256, 128>>>(ls, x);
    prep_y<<<512, 128>>>(ls, y);
    prep_b<<<512, 128>>>(b);
    rbf_main<<<dim3(128, NSL), 128>>>(ls);
    reduce_k<<<256, 256>>>(out);
}

// round 8
// speedup vs baseline: 4.0914x; 1.0354x over previous
#include <cuda_runtime.h>
#include <cuda_bf16.h>
#include <cstdint>

#define LOG2E 1.4426950408889634f
#define NP  16384
#define NT  256      // j-tiles of 64
#define NWG 1024     // i row-groups of 16
#define NSL 9        // j-slices: 4x29 + 5x28 = 256

// ---- static device scratch (no allocation) ----
__device__ uint32_t g_Xf[NWG * 32 * 16];  // a-frag image
__device__ uint32_t g_Yf[NT * 2048];      // b-frag image (GEMM1)
__device__ uint32_t g_Bf[NT * 1024];      // b-frag image (GEMM2)
__device__ float g_cxn[NP];
__device__ float g_cyn[NP];
__device__ float g_Op[NSL * NP * 16];     // per-slice fp32 partials (9 MB)

// ---- helpers ----
__device__ __forceinline__ uint32_t smem_u32(const void* p) {
    uint32_t a;
    asm("{ .reg .u64 t; cvta.to.shared.u64 t, %1; cvt.u32.u64 %0, t; }" : "=r"(a) : "l"(p));
    return a;
}
__device__ __forceinline__ void cp16(uint32_t d, const void* s) {
    asm volatile("cp.async.cg.shared.global [%0], [%1], 16;" :: "r"(d), "l"(s));
}
#define CP_COMMIT() asm volatile("cp.async.commit_group;" ::: "memory")
#define CP_WAIT0()  asm volatile("cp.async.wait_group 0;" ::: "memory")

__device__ __forceinline__ void mma_bf16(float* d, const uint32_t* a, uint32_t b0, uint32_t b1) {
    asm volatile("mma.sync.aligned.m16n8k16.row.col.f32.bf16.bf16.f32 "
                 "{%0,%1,%2,%3},{%4,%5,%6,%7},{%8,%9},{%0,%1,%2,%3};"
                 : "+f"(d[0]), "+f"(d[1]), "+f"(d[2]), "+f"(d[3])
                 : "r"(a[0]), "r"(a[1]), "r"(a[2]), "r"(a[3]), "r"(b0), "r"(b1));
}
__device__ __forceinline__ float ex2f(float a) {
    float r; asm("ex2.approx.ftz.f32 %0, %1;" : "=f"(r) : "f"(a)); return r;
}
__device__ __forceinline__ uint32_t pk2(float lo, float hi) {
    __nv_bfloat162 h = __float22bfloat162_rn(make_float2(lo, hi));
    return *(uint32_t*)&h;
}
__device__ __forceinline__ float bflo(uint32_t u) { return __uint_as_float(u << 16); }
__device__ __forceinline__ float bfhi(uint32_t u) { return __uint_as_float(u & 0xffff0000u); }
__device__ __forceinline__ uint32_t pk_split(float a, float b, int low) {
    float ah = __bfloat162float(__float2bfloat16(a));
    float bh = __bfloat162float(__float2bfloat16(b));
    return low ? pk2(a - ah, b - bh) : pk2(ah, bh);
}

// ================= prep kernels (unchanged) =================
__global__ void prep_x(const float* __restrict__ ls, const float* __restrict__ x) {
    int t = blockIdx.x * 128 + threadIdx.x;
    int wg = t >> 5, l = t & 31;
    int r0 = wg * 16 + (l >> 2), r1 = r0 + 8;
    int c = 2 * (l & 3);
    const float* x0 = x + (size_t)r0 * 32;
    const float* x1 = x + (size_t)r1 * 32;
    float v0[8], v1[8], n0 = 0.f, n1 = 0.f;
#pragma unroll
    for (int kf = 0; kf < 2; kf++)
#pragma unroll
        for (int h = 0; h < 2; h++)
#pragma unroll
            for (int e = 0; e < 2; e++) {
                int idx = kf * 4 + h * 2 + e;
                int col = kf * 16 + h * 8 + c + e;
                v0[idx] = x0[col]; v1[idx] = x1[col];
                n0 += v0[idx] * v0[idx];
                n1 += v1[idx] * v1[idx];
            }
    n0 += __shfl_xor_sync(0xffffffffu, n0, 1); n0 += __shfl_xor_sync(0xffffffffu, n0, 2);
    n1 += __shfl_xor_sync(0xffffffffu, n1, 1); n1 += __shfl_xor_sync(0xffffffffu, n1, 2);
    const float cneg = -ls[0] * LOG2E;
    if ((l & 3) == 0) { g_cxn[r0] = cneg * n0; g_cxn[r1] = cneg * n1; }

    uint32_t o[16];
#pragma unroll
    for (int s = 0; s < 2; s++)
#pragma unroll
        for (int kf = 0; kf < 2; kf++)
#pragma unroll
            for (int h = 0; h < 2; h++) {
                o[s * 8 + kf * 4 + h * 2 + 0] = pk_split(v0[kf * 4 + h * 2], v0[kf * 4 + h * 2 + 1], s);
                o[s * 8 + kf * 4 + h * 2 + 1] = pk_split(v1[kf * 4 + h * 2], v1[kf * 4 + h * 2 + 1], s);
            }
    uint4* dst = (uint4*)(g_Xf + (size_t)t * 16);
#pragma unroll
    for (int q = 0; q < 4; q++) dst[q] = make_uint4(o[4 * q], o[4 * q + 1], o[4 * q + 2], o[4 * q + 3]);
}

__global__ void prep_y(const float* __restrict__ ls, const float* __restrict__ y) {
    int t = blockIdx.x * 128 + threadIdx.x;
    int tn = t >> 5, l = t & 31;
    int j = tn * 8 + (l >> 2);
    int c = 2 * (l & 3);
    const float* yr = y + (size_t)j * 32;
    float v[8], n = 0.f;
#pragma unroll
    for (int kf = 0; kf < 2; kf++)
#pragma unroll
        for (int h = 0; h < 2; h++)
#pragma unroll
            for (int e = 0; e < 2; e++) {
                int idx = kf * 4 + h * 2 + e;
                v[idx] = yr[kf * 16 + h * 8 + c + e];
                n += v[idx] * v[idx];
            }
    n += __shfl_xor_sync(0xffffffffu, n, 1); n += __shfl_xor_sync(0xffffffffu, n, 2);
    if ((l & 3) == 0) g_cyn[j] = -ls[0] * LOG2E * n;

    uint32_t o[8];
#pragma unroll
    for (int s = 0; s < 2; s++)
#pragma unroll
        for (int kf = 0; kf < 2; kf++)
#pragma unroll
            for (int h = 0; h < 2; h++)
                o[s * 4 + kf * 2 + h] = pk_split(v[kf * 4 + h * 2], v[kf * 4 + h * 2 + 1], s);
    uint4* dst = (uint4*)(g_Yf + (size_t)tn * 256 + l * 8);
    dst[0] = make_uint4(o[0], o[1], o[2], o[3]);
    dst[1] = make_uint4(o[4], o[5], o[6], o[7]);
}

__global__ void prep_b(const float* __restrict__ b) {
    int t = blockIdx.x * 128 + threadIdx.x;
    int u = t >> 5, l = t & 31;
    int tile = u >> 3, fp = u & 7, kf = fp >> 1, nb2 = fp & 1;
    int c = nb2 * 8 + (l >> 2);
    int jb = tile * 64 + kf * 16 + 2 * (l & 3);
    float p0 = b[(size_t)jb * 16 + c];
    float p1 = b[(size_t)(jb + 1) * 16 + c];
    float p2 = b[(size_t)(jb + 8) * 16 + c];
    float p3 = b[(size_t)(jb + 9) * 16 + c];
    uint32_t h0 = pk_split(p0, p1, 0), h1 = pk_split(p2, p3, 0);
    uint32_t l0 = pk_split(p0, p1, 1), l1 = pk_split(p2, p3, 1);
    *(uint4*)(g_Bf + (size_t)tile * 1024 + fp * 128 + l * 4) = make_uint4(h0, h1, l0, l1);
}

// ================= main kernel: 4 warps x 32 i-rows = 128 i-rows/CTA =================
#define SMEM_BYTES 25088

__device__ __forceinline__ void issue_loads(uint32_t smb, int tile, int buf, int tid) {
    const char* gy = (const char*)g_Yf + (size_t)tile * 8192;
    uint32_t dy = smb + buf * 8192;
#pragma unroll
    for (int k = 0; k < 4; k++) cp16(dy + (tid + k * 128) * 16, gy + (size_t)(tid + k * 128) * 16);
    const char* gb = (const char*)g_Bf + (size_t)tile * 4096;
    uint32_t db = smb + 16384 + buf * 4096;
#pragma unroll
    for (int k = 0; k < 2; k++) cp16(db + (tid + k * 128) * 16, gb + (size_t)(tid + k * 128) * 16);
    if (tid < 16) cp16(smb + 24576 + buf * 256 + tid * 16, (const char*)(g_cyn + tile * 64) + tid * 16);
}

__global__ void __launch_bounds__(128, 4)
rbf_main(const float* __restrict__ ls) {
    __shared__ __align__(16) char sm[SMEM_BYTES];
    const uint32_t smb = smem_u32(sm);
    const int tid = threadIdx.x, w = tid >> 5, l = tid & 31;
    const int bidx = blockIdx.x;           // i-block 0..127 (128 rows each)
    const int sl = blockIdx.y;             // j-slice 0..8
    const int tstart = (sl < 4) ? 29 * sl : (116 + 28 * (sl - 4));
    const int tcnt = (sl < 4) ? 29 : 28;
    const int ig = bidx * 128 + w * 32;    // first i-row of this warp's 32

    uint32_t xfA[16], xfB[16];
    {
        const uint4* pA = (const uint4*)(g_Xf + ((size_t)(bidx * 8 + 2 * w) * 32 + l) * 16);
        const uint4* pB = (const uint4*)(g_Xf + ((size_t)(bidx * 8 + 2 * w + 1) * 32 + l) * 16);
#pragma unroll
        for (int q = 0; q < 4; q++) { *(uint4*)(xfA + 4 * q) = pA[q]; *(uint4*)(xfB + 4 * q) = pB[q]; }
    }
    const float cxnA0 = g_cxn[ig + (l >> 2)];
    const float cxnA1 = g_cxn[ig + (l >> 2) + 8];
    const float cxnB0 = g_cxn[ig + (l >> 2) + 16];
    const float cxnB1 = g_cxn[ig + (l >> 2) + 24];
    const float C2 = 2.f * __ldg(ls) * LOG2E;

    float o0A[4] = {0.f, 0.f, 0.f, 0.f}, o1A[4] = {0.f, 0.f, 0.f, 0.f};
    float o0B[4] = {0.f, 0.f, 0.f, 0.f}, o1B[4] = {0.f, 0.f, 0.f, 0.f};

    issue_loads(smb, tstart, 0, tid);
    CP_COMMIT();

    for (int tt = 0; tt < tcnt; tt++) {
        CP_WAIT0();
        __syncthreads();
        if (tt + 1 < tcnt) { issue_loads(smb, tstart + tt + 1, (tt + 1) & 1, tid); CP_COMMIT(); }
        const int buf = tt & 1;
        const char* syb = sm + buf * 8192;
        const char* sbb = sm + 16384 + buf * 4096;
        const char* scy = sm + 24576 + buf * 256;

#pragma unroll
        for (int g = 0; g < 4; g++) {
            uint32_t wahA[4], walA[4], wahB[4], walB[4];
#pragma unroll
            for (int h = 0; h < 2; h++) {
                const int nb = g * 2 + h;
                uint4 y0 = *(const uint4*)(syb + nb * 1024 + l * 32);
                uint4 y1 = *(const uint4*)(syb + nb * 1024 + l * 32 + 16);
                // 4 independent accumulator chains (depth 3), round-robin interleave:
                float sA0[4] = {0.f, 0.f, 0.f, 0.f}, sA1[4] = {0.f, 0.f, 0.f, 0.f};
                float sB0[4] = {0.f, 0.f, 0.f, 0.f}, sB1[4] = {0.f, 0.f, 0.f, 0.f};
                mma_bf16(sA0, xfA + 0,  y0.x, y0.y);   // Xh·Yh k0
                mma_bf16(sB0, xfB + 0,  y0.x, y0.y);
                mma_bf16(sA1, xfA + 4,  y0.z, y0.w);   // Xh·Yh k1
                mma_bf16(sB1, xfB + 4,  y0.z, y0.w);
                mma_bf16(sA0, xfA + 0,  y1.x, y1.y);   // Xh·Yl k0
                mma_bf16(sB0, xfB + 0,  y1.x, y1.y);
                mma_bf16(sA1, xfA + 4,  y1.z, y1.w);   // Xh·Yl k1
                mma_bf16(sB1, xfB + 4,  y1.z, y1.w);
                mma_bf16(sA0, xfA + 8,  y0.x, y0.y);   // Xl·Yh k0
                mma_bf16(sB0, xfB + 8,  y0.x, y0.y);
                mma_bf16(sA1, xfA + 12, y0.z, y0.w);   // Xl·Yh k1
                mma_bf16(sB1, xfB + 12, y0.z, y0.w);

                float2 cy = *(const float2*)(scy + nb * 32 + (l & 3) * 8);
                // half A epilogue
                {
                    float w0 = ex2f(fminf(fmaf(C2, sA0[0] + sA1[0], cxnA0 + cy.x), 0.f));
                    float w1 = ex2f(fminf(fmaf(C2, sA0[1] + sA1[1], cxnA0 + cy.y), 0.f));
                    float w2 = ex2f(fminf(fmaf(C2, sA0[2] + sA1[2], cxnA1 + cy.x), 0.f));
                    float w3 = ex2f(fminf(fmaf(C2, sA0[3] + sA1[3], cxnA1 + cy.y), 0.f));
                    uint32_t h01 = pk2(w0, w1), h23 = pk2(w2, w3);
                    wahA[h * 2] = h01; wahA[h * 2 + 1] = h23;
                    walA[h * 2] = pk2(w0 - bflo(h01), w1 - bfhi(h01));
                    walA[h * 2 + 1] = pk2(w2 - bflo(h23), w3 - bfhi(h23));
                }
                // half B epilogue
                {
                    float w0 = ex2f(fminf(fmaf(C2, sB0[0] + sB1[0], cxnB0 + cy.x), 0.f));
                    float w1 = ex2f(fminf(fmaf(C2, sB0[1] + sB1[1], cxnB0 + cy.y), 0.f));
                    float w2 = ex2f(fminf(fmaf(C2, sB0[2] + sB1[2], cxnB1 + cy.x), 0.f));
                    float w3 = ex2f(fminf(fmaf(C2, sB0[3] + sB1[3], cxnB1 + cy.y), 0.f));
                    uint32_t h01 = pk2(w0, w1), h23 = pk2(w2, w3);
                    wahB[h * 2] = h01; wahB[h * 2 + 1] = h23;
                    walB[h * 2] = pk2(w0 - bflo(h01), w1 - bfhi(h01));
                    walB[h * 2 + 1] = pk2(w2 - bflo(h23), w3 - bfhi(h23));
                }
            }
            // GEMM2: 4 accumulator chains round-robin (per-accumulator term order: Bh, Bl, Wl·Bh)
            uint4 b0 = *(const uint4*)(sbb + (g * 2) * 512 + l * 16);
            uint4 b1 = *(const uint4*)(sbb + (g * 2 + 1) * 512 + l * 16);
            mma_bf16(o0A, wahA, b0.x, b0.y);
            mma_bf16(o0B, wahB, b0.x, b0.y);
            mma_bf16(o1A, wahA, b1.x, b1.y);
            mma_bf16(o1B, wahB, b1.x, b1.y);
            mma_bf16(o0A, wahA, b0.z, b0.w);
            mma_bf16(o0B, wahB, b0.z, b0.w);
            mma_bf16(o1A, wahA, b1.z, b1.w);
            mma_bf16(o1B, wahB, b1.z, b1.w);
            mma_bf16(o0A, walA, b0.x, b0.y);
            mma_bf16(o0B, walB, b0.x, b0.y);
            mma_bf16(o1A, walA, b1.x, b1.y);
            mma_bf16(o1B, walB, b1.x, b1.y);
        }
    }

    // partial write: slice-local buffer
    float* op = g_Op + (size_t)sl * (NP * 16);
    const int cb = 2 * (l & 3);
    const int rA = ig + (l >> 2), rB = rA + 16;
    *(float2*)(op + (size_t)rA * 16 + cb)            = make_float2(o0A[0], o0A[1]);
    *(float2*)(op + (size_t)rA * 16 + 8 + cb)        = make_float2(o1A[0], o1A[1]);
    *(float2*)(op + (size_t)(rA + 8) * 16 + cb)      = make_float2(o0A[2], o0A[3]);
    *(float2*)(op + (size_t)(rA + 8) * 16 + 8 + cb)  = make_float2(o1A[2], o1A[3]);
    *(float2*)(op + (size_t)rB * 16 + cb)            = make_float2(o0B[0], o0B[1]);
    *(float2*)(op + (size_t)rB * 16 + 8 + cb)        = make_float2(o1B[0], o1B[1]);
    *(float2*)(op + (size_t)(rB + 8) * 16 + cb)      = make_float2(o0B[2], o0B[3]);
    *(float2*)(op + (size_t)(rB + 8) * 16 + 8 + cb)  = make_float2(o1B[2], o1B[3]);
}

// ================= deterministic slice reduction =================
__global__ void reduce_k(float* __restrict__ out) {
    int idx = blockIdx.x * 256 + threadIdx.x;
    float4 o = ((const float4*)g_Op)[idx];
#pragma unroll
    for (int s = 1; s < NSL; s++) {
        float4 v = ((const float4*)(g_Op + (size_t)s * NP * 16))[idx];
        o.x += v.x; o.y += v.y; o.z += v.z; o.w += v.w;   // fixed slice order
    }
    ((float4*)out)[idx] = o;
}

extern "C" void kernel_launch(void* const* d_in, const int* in_sizes, int n_in,
                              void* d_out, int out_size) {
    const float* ls = (const float*)d_in[0];
    const float* x  = (const float*)d_in[1];
    const float* y  = (const float*)d_in[2];
    const float* b  = (const float*)d_in[3];
    float* out = (float*)d_out;

    prep_x<<<256, 128>>>(ls, x);
    prep_y<<<512, 128>>>(ls, y);
    prep_b<<<512, 128>>>(b);
    rbf_main<<<dim3(128, NSL), 128>>>(ls);
    reduce_k<<<256, 256>>>(out);
}

// round 9
// speedup vs baseline: 4.2676x; 1.0431x over previous
#include <cuda_runtime.h>
#include <cuda_bf16.h>
#include <cstdint>

#define LOG2E 1.4426950408889634f
#define NP  16384
#define NT  256      // j-tiles of 64
#define NWG 1024     // i row-groups of 16
#define NSL 9        // j-slices: 4x29 + 5x28 = 256

// ---- static device scratch (no allocation) ----
__device__ uint32_t g_Xf[NWG * 32 * 16];  // a-frag image
__device__ uint32_t g_Yf[NT * 2048];      // b-frag image (GEMM1)
__device__ uint32_t g_Bf[NT * 1024];      // b-frag image (GEMM2)
__device__ float g_cxn[NP];
__device__ float g_cyn[NP];
__device__ float g_Op[NSL * NP * 16];     // per-slice fp32 partials (9 MB)

// ---- helpers ----
__device__ __forceinline__ uint32_t smem_u32(const void* p) {
    uint32_t a;
    asm("{ .reg .u64 t; cvta.to.shared.u64 t, %1; cvt.u32.u64 %0, t; }" : "=r"(a) : "l"(p));
    return a;
}
__device__ __forceinline__ void cp16(uint32_t d, const void* s) {
    asm volatile("cp.async.cg.shared.global [%0], [%1], 16;" :: "r"(d), "l"(s));
}
#define CP_COMMIT() asm volatile("cp.async.commit_group;" ::: "memory")
#define CP_WAIT0()  asm volatile("cp.async.wait_group 0;" ::: "memory")

__device__ __forceinline__ void mma_bf16(float* d, const uint32_t* a, uint32_t b0, uint32_t b1) {
    asm volatile("mma.sync.aligned.m16n8k16.row.col.f32.bf16.bf16.f32 "
                 "{%0,%1,%2,%3},{%4,%5,%6,%7},{%8,%9},{%0,%1,%2,%3};"
                 : "+f"(d[0]), "+f"(d[1]), "+f"(d[2]), "+f"(d[3])
                 : "r"(a[0]), "r"(a[1]), "r"(a[2]), "r"(a[3]), "r"(b0), "r"(b1));
}
__device__ __forceinline__ float ex2f(float a) {
    float r; asm("ex2.approx.ftz.f32 %0, %1;" : "=f"(r) : "f"(a)); return r;
}
__device__ __forceinline__ uint32_t pk2(float lo, float hi) {
    __nv_bfloat162 h = __float22bfloat162_rn(make_float2(lo, hi));
    return *(uint32_t*)&h;
}
__device__ __forceinline__ float bflo(uint32_t u) { return __uint_as_float(u << 16); }
__device__ __forceinline__ float bfhi(uint32_t u) { return __uint_as_float(u & 0xffff0000u); }
__device__ __forceinline__ uint32_t pk_split(float a, float b, int low) {
    float ah = __bfloat162float(__float2bfloat16(a));
    float bh = __bfloat162float(__float2bfloat16(b));
    return low ? pk2(a - ah, b - bh) : pk2(ah, bh);
}

// ================= prep kernels (unchanged) =================
__global__ void prep_x(const float* __restrict__ ls, const float* __restrict__ x) {
    int t = blockIdx.x * 128 + threadIdx.x;
    int wg = t >> 5, l = t & 31;
    int r0 = wg * 16 + (l >> 2), r1 = r0 + 8;
    int c = 2 * (l & 3);
    const float* x0 = x + (size_t)r0 * 32;
    const float* x1 = x + (size_t)r1 * 32;
    float v0[8], v1[8], n0 = 0.f, n1 = 0.f;
#pragma unroll
    for (int kf = 0; kf < 2; kf++)
#pragma unroll
        for (int h = 0; h < 2; h++)
#pragma unroll
            for (int e = 0; e < 2; e++) {
                int idx = kf * 4 + h * 2 + e;
                int col = kf * 16 + h * 8 + c + e;
                v0[idx] = x0[col]; v1[idx] = x1[col];
                n0 += v0[idx] * v0[idx];
                n1 += v1[idx] * v1[idx];
            }
    n0 += __shfl_xor_sync(0xffffffffu, n0, 1); n0 += __shfl_xor_sync(0xffffffffu, n0, 2);
    n1 += __shfl_xor_sync(0xffffffffu, n1, 1); n1 += __shfl_xor_sync(0xffffffffu, n1, 2);
    const float cneg = -ls[0] * LOG2E;
    if ((l & 3) == 0) { g_cxn[r0] = cneg * n0; g_cxn[r1] = cneg * n1; }

    uint32_t o[16];
#pragma unroll
    for (int s = 0; s < 2; s++)
#pragma unroll
        for (int kf = 0; kf < 2; kf++)
#pragma unroll
            for (int h = 0; h < 2; h++) {
                o[s * 8 + kf * 4 + h * 2 + 0] = pk_split(v0[kf * 4 + h * 2], v0[kf * 4 + h * 2 + 1], s);
                o[s * 8 + kf * 4 + h * 2 + 1] = pk_split(v1[kf * 4 + h * 2], v1[kf * 4 + h * 2 + 1], s);
            }
    uint4* dst = (uint4*)(g_Xf + (size_t)t * 16);
#pragma unroll
    for (int q = 0; q < 4; q++) dst[q] = make_uint4(o[4 * q], o[4 * q + 1], o[4 * q + 2], o[4 * q + 3]);
}

__global__ void prep_y(const float* __restrict__ ls, const float* __restrict__ y) {
    int t = blockIdx.x * 128 + threadIdx.x;
    int tn = t >> 5, l = t & 31;
    int j = tn * 8 + (l >> 2);
    int c = 2 * (l & 3);
    const float* yr = y + (size_t)j * 32;
    float v[8], n = 0.f;
#pragma unroll
    for (int kf = 0; kf < 2; kf++)
#pragma unroll
        for (int h = 0; h < 2; h++)
#pragma unroll
            for (int e = 0; e < 2; e++) {
                int idx = kf * 4 + h * 2 + e;
                v[idx] = yr[kf * 16 + h * 8 + c + e];
                n += v[idx] * v[idx];
            }
    n += __shfl_xor_sync(0xffffffffu, n, 1); n += __shfl_xor_sync(0xffffffffu, n, 2);
    if ((l & 3) == 0) g_cyn[j] = -ls[0] * LOG2E * n;

    uint32_t o[8];
#pragma unroll
    for (int s = 0; s < 2; s++)
#pragma unroll
        for (int kf = 0; kf < 2; kf++)
#pragma unroll
            for (int h = 0; h < 2; h++)
                o[s * 4 + kf * 2 + h] = pk_split(v[kf * 4 + h * 2], v[kf * 4 + h * 2 + 1], s);
    uint4* dst = (uint4*)(g_Yf + (size_t)tn * 256 + l * 8);
    dst[0] = make_uint4(o[0], o[1], o[2], o[3]);
    dst[1] = make_uint4(o[4], o[5], o[6], o[7]);
}

__global__ void prep_b(const float* __restrict__ b) {
    int t = blockIdx.x * 128 + threadIdx.x;
    int u = t >> 5, l = t & 31;
    int tile = u >> 3, fp = u & 7, kf = fp >> 1, nb2 = fp & 1;
    int c = nb2 * 8 + (l >> 2);
    int jb = tile * 64 + kf * 16 + 2 * (l & 3);
    float p0 = b[(size_t)jb * 16 + c];
    float p1 = b[(size_t)(jb + 1) * 16 + c];
    float p2 = b[(size_t)(jb + 8) * 16 + c];
    float p3 = b[(size_t)(jb + 9) * 16 + c];
    uint32_t h0 = pk_split(p0, p1, 0), h1 = pk_split(p2, p3, 0);
    uint32_t l0 = pk_split(p0, p1, 1), l1 = pk_split(p2, p3, 1);
    *(uint4*)(g_Bf + (size_t)tile * 1024 + fp * 128 + l * 4) = make_uint4(h0, h1, l0, l1);
}

// ================= main kernel: 4 warps x 32 i-rows = 128 i-rows/CTA =================
#define SMEM_BYTES 25088

__device__ __forceinline__ void issue_loads(uint32_t smb, int tile, int buf, int tid) {
    const char* gy = (const char*)g_Yf + (size_t)tile * 8192;
    uint32_t dy = smb + buf * 8192;
#pragma unroll
    for (int k = 0; k < 4; k++) cp16(dy + (tid + k * 128) * 16, gy + (size_t)(tid + k * 128) * 16);
    const char* gb = (const char*)g_Bf + (size_t)tile * 4096;
    uint32_t db = smb + 16384 + buf * 4096;
#pragma unroll
    for (int k = 0; k < 2; k++) cp16(db + (tid + k * 128) * 16, gb + (size_t)(tid + k * 128) * 16);
    if (tid < 16) cp16(smb + 24576 + buf * 256 + tid * 16, (const char*)(g_cyn + tile * 64) + tid * 16);
}

__global__ void __launch_bounds__(128, 4)
rbf_main(const float* __restrict__ ls) {
    __shared__ __align__(16) char sm[SMEM_BYTES];
    const uint32_t smb = smem_u32(sm);
    const int tid = threadIdx.x, w = tid >> 5, l = tid & 31;
    const int bidx = blockIdx.x;           // i-block 0..127 (128 rows each)
    const int sl = blockIdx.y;             // j-slice 0..8
    const int tstart = (sl < 4) ? 29 * sl : (116 + 28 * (sl - 4));
    const int tcnt = (sl < 4) ? 29 : 28;
    const int ig = bidx * 128 + w * 32;    // first i-row of this warp's 32

    uint32_t xfA[16], xfB[16];
    {
        const uint4* pA = (const uint4*)(g_Xf + ((size_t)(bidx * 8 + 2 * w) * 32 + l) * 16);
        const uint4* pB = (const uint4*)(g_Xf + ((size_t)(bidx * 8 + 2 * w + 1) * 32 + l) * 16);
#pragma unroll
        for (int q = 0; q < 4; q++) { *(uint4*)(xfA + 4 * q) = pA[q]; *(uint4*)(xfB + 4 * q) = pB[q]; }
    }
    const float cxnA0 = g_cxn[ig + (l >> 2)];
    const float cxnA1 = g_cxn[ig + (l >> 2) + 8];
    const float cxnB0 = g_cxn[ig + (l >> 2) + 16];
    const float cxnB1 = g_cxn[ig + (l >> 2) + 24];
    const float C2 = 2.f * __ldg(ls) * LOG2E;

    float o0A[4] = {0.f, 0.f, 0.f, 0.f}, o1A[4] = {0.f, 0.f, 0.f, 0.f};
    float o0B[4] = {0.f, 0.f, 0.f, 0.f}, o1B[4] = {0.f, 0.f, 0.f, 0.f};

    issue_loads(smb, tstart, 0, tid);
    CP_COMMIT();

    for (int tt = 0; tt < tcnt; tt++) {
        CP_WAIT0();
        __syncthreads();
        if (tt + 1 < tcnt) { issue_loads(smb, tstart + tt + 1, (tt + 1) & 1, tid); CP_COMMIT(); }
        const int buf = tt & 1;
        const char* syb = sm + buf * 8192;
        const char* sbb = sm + 16384 + buf * 4096;
        const char* scy = sm + 24576 + buf * 256;

        // double-slot register staging for the g-pipeline
        uint4 yv[2][4];     // [slot][h*2 + half]: y frag pairs for h0,h1
        uint4 bv[2][2];
        float2 cyv[2][2];

#define LOADG(gg, slot) do { \
            const char* yb0 = syb + ((gg) * 2) * 1024 + l * 32; \
            const char* yb1 = syb + ((gg) * 2 + 1) * 1024 + l * 32; \
            yv[slot][0] = *(const uint4*)yb0; \
            yv[slot][1] = *(const uint4*)(yb0 + 16); \
            yv[slot][2] = *(const uint4*)yb1; \
            yv[slot][3] = *(const uint4*)(yb1 + 16); \
            bv[slot][0] = *(const uint4*)(sbb + ((gg) * 2) * 512 + l * 16); \
            bv[slot][1] = *(const uint4*)(sbb + ((gg) * 2 + 1) * 512 + l * 16); \
            cyv[slot][0] = *(const float2*)(scy + ((gg) * 2) * 32 + (l & 3) * 8); \
            cyv[slot][1] = *(const float2*)(scy + ((gg) * 2 + 1) * 32 + (l & 3) * 8); \
        } while (0)

        LOADG(0, 0);

#pragma unroll
        for (int g = 0; g < 4; g++) {
            const int p = g & 1, q = p ^ 1;
            uint32_t wahA[4], walA[4], wahB[4], walB[4];
            // ---- GEMM1 bursts: h0 then h1, 4 chains round-robin each ----
            float sA0[4] = {0.f, 0.f, 0.f, 0.f}, sA1[4] = {0.f, 0.f, 0.f, 0.f};
            float sB0[4] = {0.f, 0.f, 0.f, 0.f}, sB1[4] = {0.f, 0.f, 0.f, 0.f};
            float tA0[4] = {0.f, 0.f, 0.f, 0.f}, tA1[4] = {0.f, 0.f, 0.f, 0.f};
            float tB0[4] = {0.f, 0.f, 0.f, 0.f}, tB1[4] = {0.f, 0.f, 0.f, 0.f};
            {
                uint4 y0 = yv[p][0], y1 = yv[p][1];
                mma_bf16(sA0, xfA + 0,  y0.x, y0.y);
                mma_bf16(sB0, xfB + 0,  y0.x, y0.y);
                mma_bf16(sA1, xfA + 4,  y0.z, y0.w);
                mma_bf16(sB1, xfB + 4,  y0.z, y0.w);
                mma_bf16(sA0, xfA + 0,  y1.x, y1.y);
                mma_bf16(sB0, xfB + 0,  y1.x, y1.y);
                mma_bf16(sA1, xfA + 4,  y1.z, y1.w);
                mma_bf16(sB1, xfB + 4,  y1.z, y1.w);
                mma_bf16(sA0, xfA + 8,  y0.x, y0.y);
                mma_bf16(sB0, xfB + 8,  y0.x, y0.y);
                mma_bf16(sA1, xfA + 12, y0.z, y0.w);
                mma_bf16(sB1, xfB + 12, y0.z, y0.w);
            }
            {
                uint4 y0 = yv[p][2], y1 = yv[p][3];
                mma_bf16(tA0, xfA + 0,  y0.x, y0.y);
                mma_bf16(tB0, xfB + 0,  y0.x, y0.y);
                mma_bf16(tA1, xfA + 4,  y0.z, y0.w);
                mma_bf16(tB1, xfB + 4,  y0.z, y0.w);
                mma_bf16(tA0, xfA + 0,  y1.x, y1.y);
                mma_bf16(tB0, xfB + 0,  y1.x, y1.y);
                mma_bf16(tA1, xfA + 4,  y1.z, y1.w);
                mma_bf16(tB1, xfB + 4,  y1.z, y1.w);
                mma_bf16(tA0, xfA + 8,  y0.x, y0.y);
                mma_bf16(tB0, xfB + 8,  y0.x, y0.y);
                mma_bf16(tA1, xfA + 12, y0.z, y0.w);
                mma_bf16(tB1, xfB + 12, y0.z, y0.w);
            }

            // ---- prefetch next g (LDS hides under epilogues) ----
            if (g < 3) LOADG(g + 1, q);

            // ---- epilogue h0 ----
            {
                float2 cy = cyv[p][0];
                float w0 = ex2f(fminf(fmaf(C2, sA0[0] + sA1[0], cxnA0 + cy.x), 0.f));
                float w1 = ex2f(fminf(fmaf(C2, sA0[1] + sA1[1], cxnA0 + cy.y), 0.f));
                float w2 = ex2f(fminf(fmaf(C2, sA0[2] + sA1[2], cxnA1 + cy.x), 0.f));
                float w3 = ex2f(fminf(fmaf(C2, sA0[3] + sA1[3], cxnA1 + cy.y), 0.f));
                uint32_t h01 = pk2(w0, w1), h23 = pk2(w2, w3);
                wahA[0] = h01; wahA[1] = h23;
                walA[0] = pk2(w0 - bflo(h01), w1 - bfhi(h01));
                walA[1] = pk2(w2 - bflo(h23), w3 - bfhi(h23));
                float v0 = ex2f(fminf(fmaf(C2, sB0[0] + sB1[0], cxnB0 + cy.x), 0.f));
                float v1 = ex2f(fminf(fmaf(C2, sB0[1] + sB1[1], cxnB0 + cy.y), 0.f));
                float v2 = ex2f(fminf(fmaf(C2, sB0[2] + sB1[2], cxnB1 + cy.x), 0.f));
                float v3 = ex2f(fminf(fmaf(C2, sB0[3] + sB1[3], cxnB1 + cy.y), 0.f));
                uint32_t g01 = pk2(v0, v1), g23 = pk2(v2, v3);
                wahB[0] = g01; wahB[1] = g23;
                walB[0] = pk2(v0 - bflo(g01), v1 - bfhi(g01));
                walB[1] = pk2(v2 - bflo(g23), v3 - bfhi(g23));
            }
            // ---- epilogue h1 ----
            {
                float2 cy = cyv[p][1];
                float w0 = ex2f(fminf(fmaf(C2, tA0[0] + tA1[0], cxnA0 + cy.x), 0.f));
                float w1 = ex2f(fminf(fmaf(C2, tA0[1] + tA1[1], cxnA0 + cy.y), 0.f));
                float w2 = ex2f(fminf(fmaf(C2, tA0[2] + tA1[2], cxnA1 + cy.x), 0.f));
                float w3 = ex2f(fminf(fmaf(C2, tA0[3] + tA1[3], cxnA1 + cy.y), 0.f));
                uint32_t h01 = pk2(w0, w1), h23 = pk2(w2, w3);
                wahA[2] = h01; wahA[3] = h23;
                walA[2] = pk2(w0 - bflo(h01), w1 - bfhi(h01));
                walA[3] = pk2(w2 - bflo(h23), w3 - bfhi(h23));
                float v0 = ex2f(fminf(fmaf(C2, tB0[0] + tB1[0], cxnB0 + cy.x), 0.f));
                float v1 = ex2f(fminf(fmaf(C2, tB0[1] + tB1[1], cxnB0 + cy.y), 0.f));
                float v2 = ex2f(fminf(fmaf(C2, tB0[2] + tB1[2], cxnB1 + cy.x), 0.f));
                float v3 = ex2f(fminf(fmaf(C2, tB0[3] + tB1[3], cxnB1 + cy.y), 0.f));
                uint32_t g01 = pk2(v0, v1), g23 = pk2(v2, v3);
                wahB[2] = g01; wahB[3] = g23;
                walB[2] = pk2(v0 - bflo(g01), v1 - bfhi(g01));
                walB[3] = pk2(v2 - bflo(g23), v3 - bfhi(g23));
            }
            // ---- GEMM2: 4 accumulator chains round-robin ----
            uint4 b0 = bv[p][0], b1 = bv[p][1];
            mma_bf16(o0A, wahA, b0.x, b0.y);
            mma_bf16(o0B, wahB, b0.x, b0.y);
            mma_bf16(o1A, wahA, b1.x, b1.y);
            mma_bf16(o1B, wahB, b1.x, b1.y);
            mma_bf16(o0A, wahA, b0.z, b0.w);
            mma_bf16(o0B, wahB, b0.z, b0.w);
            mma_bf16(o1A, wahA, b1.z, b1.w);
            mma_bf16(o1B, wahB, b1.z, b1.w);
            mma_bf16(o0A, walA, b0.x, b0.y);
            mma_bf16(o0B, walB, b0.x, b0.y);
            mma_bf16(o1A, walA, b1.x, b1.y);
            mma_bf16(o1B, walB, b1.x, b1.y);
        }
#undef LOADG
    }

    // partial write: slice-local buffer
    float* op = g_Op + (size_t)sl * (NP * 16);
    const int cb = 2 * (l & 3);
    const int rA = ig + (l >> 2), rB = rA + 16;
    *(float2*)(op + (size_t)rA * 16 + cb)            = make_float2(o0A[0], o0A[1]);
    *(float2*)(op + (size_t)rA * 16 + 8 + cb)        = make_float2(o1A[0], o1A[1]);
    *(float2*)(op + (size_t)(rA + 8) * 16 + cb)      = make_float2(o0A[2], o0A[3]);
    *(float2*)(op + (size_t)(rA + 8) * 16 + 8 + cb)  = make_float2(o1A[2], o1A[3]);
    *(float2*)(op + (size_t)rB * 16 + cb)            = make_float2(o0B[0], o0B[1]);
    *(float2*)(op + (size_t)rB * 16 + 8 + cb)        = make_float2(o1B[0], o1B[1]);
    *(float2*)(op + (size_t)(rB + 8) * 16 + cb)      = make_float2(o0B[2], o0B[3]);
    *(float2*)(op + (size_t)(rB + 8) * 16 + 8 + cb)  = make_float2(o1B[2], o1B[3]);
}

// ================= deterministic slice reduction =================
__global__ void reduce_k(float* __restrict__ out) {
    int idx = blockIdx.x * 256 + threadIdx.x;
    float4 o = ((const float4*)g_Op)[idx];
#pragma unroll
    for (int s = 1; s < NSL; s++) {
        float4 v = ((const float4*)(g_Op + (size_t)s * NP * 16))[idx];
        o.x += v.x; o.y += v.y; o.z += v.z; o.w += v.w;   // fixed slice order
    }
    ((float4*)out)[idx] = o;
}

extern "C" void kernel_launch(void* const* d_in, const int* in_sizes, int n_in,
                              void* d_out, int out_size) {
    const float* ls = (const float*)d_in[0];
    const float* x  = (const float*)d_in[1];
    const float* y  = (const float*)d_in[2];
    const float* b  = (const float*)d_in[3];
    float* out = (float*)d_out;

    prep_x<<<256, 128>>>(ls, x);
    prep_y<<<512, 128>>>(ls, y);
    prep_b<<<512, 128>>>(b);
    rbf_main<<<dim3(128, NSL), 128>>>(ls);
    reduce_k<<<256, 256>>>(out);
}